// round 12
// baseline (speedup 1.0000x reference)
#include <cuda_runtime.h>
#include <cuda_fp16.h>
#include <math.h>

#define BATCH 2
#define SEQ   2048
#define NH    16
#define DHEAD 64
#define DM    1024
#define TTOK  (BATCH*SEQ)
#define BHN   (BATCH*NH)
#define ATTN_OFF ((size_t)BATCH*SEQ*DM)
#define LN_EPS 1e-5f

__device__ half  g_qh[(size_t)BHN*SEQ*DHEAD];    // [B,H,S,64] fp16
__device__ half  g_kh[(size_t)BHN*SEQ*DHEAD];    // [B,H,S,64] fp16
__device__ half  g_vh[(size_t)BHN*DHEAD*SEQ];    // [B,H,64,S] fp16 transposed
__device__ float g_ctx[(size_t)TTOK*DM];          // [T, H*64]
__device__ float g_x[(size_t)TTOK*DM];            // pre-LN

__device__ __forceinline__ unsigned tf32(float f) {
    unsigned u;
    asm("cvt.rna.tf32.f32 %0, %1;" : "=r"(u) : "f"(f));
    return u;
}
__device__ __forceinline__ unsigned h2pack(float x, float y) {
    __half2 h = __floats2half2_rn(x, y);
    return *(unsigned*)&h;
}

#define MMA(d, a, b) \
    asm volatile("mma.sync.aligned.m16n8k8.row.col.f32.tf32.tf32.f32 " \
        "{%0,%1,%2,%3}, {%4,%5,%6,%7}, {%8,%9}, {%0,%1,%2,%3};" \
        : "+f"((d)[0]), "+f"((d)[1]), "+f"((d)[2]), "+f"((d)[3]) \
        : "r"((a)[0]), "r"((a)[1]), "r"((a)[2]), "r"((a)[3]), \
          "r"((b)[0]), "r"((b)[1]))

#define MMA16816(d, a0,a1,a2,a3, b0,b1) \
    asm volatile("mma.sync.aligned.m16n8k16.row.col.f32.f16.f16.f32 " \
        "{%0,%1,%2,%3}, {%4,%5,%6,%7}, {%8,%9}, {%0,%1,%2,%3};" \
        : "+f"((d)[0]), "+f"((d)[1]), "+f"((d)[2]), "+f"((d)[3]) \
        : "r"(a0), "r"(a1), "r"(a2), "r"(a3), "r"(b0), "r"(b1))

#define CPA16(dst, src) \
    asm volatile("cp.async.ca.shared.global [%0], [%1], 16;\n" \
        :: "r"((unsigned)(dst)), "l"((const void*)(src)))
#define CP_COMMIT() asm volatile("cp.async.commit_group;\n")
#define CP_WAIT1()  asm volatile("cp.async.wait_group 1;\n")

// One K=16 chunk of mma work for the projection kernels (As/Bs chunked).
#define MMA_STEP(NMT, NNT) \
    _Pragma("unroll") \
    for (int kk = 0; kk < 16; kk += 8) { \
        unsigned af[NMT][4]; unsigned bf[NNT][2]; \
        _Pragma("unroll") \
        for (int mt = 0; mt < NMT; mt++) { \
            int mr = wm + mt*16 + g; \
            af[mt][0] = As[mr][kk+t];   af[mt][1] = As[mr+8][kk+t]; \
            af[mt][2] = As[mr][kk+t+4]; af[mt][3] = As[mr+8][kk+t+4]; \
        } \
        _Pragma("unroll") \
        for (int nt = 0; nt < NNT; nt++) { \
            bf[nt][0] = Bs[kk+t][wn + nt*8 + g]; \
            bf[nt][1] = Bs[kk+t+4][wn + nt*8 + g]; \
        } \
        _Pragma("unroll") \
        for (int mt = 0; mt < NMT; mt++) \
            _Pragma("unroll") \
            for (int nt = 0; nt < NNT; nt++) \
                MMA(acc[mt][nt], af[mt], bf[nt]); \
    }

// ===========================================================================
// QKV projection (tf32 mma). Q/K: fp16 [B,H,S,64]. V: fp16 [B,H,64,S].
// ===========================================================================
__global__ void __launch_bounds__(256) qkv_kernel(
    const float* __restrict__ Qin, const float* __restrict__ Kin,
    const float* __restrict__ Vin,
    const float* __restrict__ Wq, const float* __restrict__ Wk,
    const float* __restrict__ Wv,
    const float* __restrict__ bq, const float* __restrict__ bk,
    const float* __restrict__ bv)
{
    __shared__ unsigned As[128][20];
    __shared__ unsigned Bs[16][136];

    const int z = blockIdx.z;
    const float* X    = (z == 0) ? Qin : (z == 1) ? Kin : Vin;
    const float* W    = (z == 0) ? Wq  : (z == 1) ? Wk  : Wv;
    const float* bias = (z == 0) ? bq  : (z == 1) ? bk  : bv;

    const int tid = threadIdx.x;
    const int lane = tid & 31, wid = tid >> 5;
    const int g = lane >> 2, t = lane & 3;
    const int wm = (wid & 1) << 6;
    const int wn = (wid >> 1) << 5;
    const int m0 = blockIdx.y * 128, n0 = blockIdx.x * 128;

    const int ar = tid >> 2, ak = (tid & 3) << 2;
    const int br = tid >> 5, bn = (tid & 31) << 2;

    const float* Ap = X + (size_t)(m0 + ar) * DM + ak;
    const float* Bp = W + (size_t)br * DM + n0 + bn;

    float acc[4][4][4] = {};
    float4 pa0, pa1, pb0, pb1;

    #define QKV_LDG(k0) do { \
        pa0 = *(const float4*)(Ap + (k0)); \
        pa1 = *(const float4*)(Ap + (size_t)64 * DM + (k0)); \
        pb0 = *(const float4*)(Bp + (size_t)(k0) * DM); \
        pb1 = *(const float4*)(Bp + (size_t)((k0) + 8) * DM); } while(0)

    #define QKV_STS() do { \
        *(uint4*)&As[ar][ak]    = make_uint4(tf32(pa0.x), tf32(pa0.y), tf32(pa0.z), tf32(pa0.w)); \
        *(uint4*)&As[ar+64][ak] = make_uint4(tf32(pa1.x), tf32(pa1.y), tf32(pa1.z), tf32(pa1.w)); \
        *(uint4*)&Bs[br][bn]    = make_uint4(tf32(pb0.x), tf32(pb0.y), tf32(pb0.z), tf32(pb0.w)); \
        *(uint4*)&Bs[br+8][bn]  = make_uint4(tf32(pb1.x), tf32(pb1.y), tf32(pb1.z), tf32(pb1.w)); } while(0)

    QKV_LDG(0);
    QKV_STS();
    __syncthreads();
    for (int k0 = 16; k0 < DM; k0 += 16) {
        QKV_LDG(k0);
        MMA_STEP(4, 4);
        __syncthreads();
        QKV_STS();
        __syncthreads();
    }
    MMA_STEP(4, 4);

    #pragma unroll
    for (int nt = 0; nt < 4; nt++) {
        int c = n0 + wn + nt*8 + 2*t;
        int h = c >> 6, d = c & 63;
        float2 bi = *(const float2*)(bias + c);
        #pragma unroll
        for (int mt = 0; mt < 4; mt++) {
            int r = m0 + wm + mt*16 + g;
            int b = r >> 11, s = r & (SEQ - 1);
            int bh = b * NH + h;
            float v0 = acc[mt][nt][0] + bi.x;
            float v1 = acc[mt][nt][1] + bi.y;
            float v2 = acc[mt][nt][2] + bi.x;
            float v3 = acc[mt][nt][3] + bi.y;
            if (z == 2) {
                half* vb = g_vh + ((size_t)bh * DHEAD + d) * SEQ;
                vb[s]          = __float2half(v0);
                vb[SEQ + s]    = __float2half(v1);
                vb[s + 8]      = __float2half(v2);
                vb[SEQ + s + 8]= __float2half(v3);
            } else {
                half* out = (z == 0) ? g_qh : g_kh;
                half* op = out + ((size_t)bh * SEQ + s) * DHEAD + d;
                *(unsigned*)op = h2pack(v0, v1);
                op += (size_t)8 * DHEAD;
                *(unsigned*)op = h2pack(v2, v3);
            }
        }
    }
}

// ===========================================================================
// Output projection (tf32 mma): g_x = g_ctx @ Wo + bo + residual.
// ===========================================================================
__global__ void __launch_bounds__(256) oproj_kernel(
    const float* __restrict__ W, const float* __restrict__ bias,
    const float* __restrict__ resid)
{
    __shared__ unsigned As[128][20];
    __shared__ unsigned Bs[16][136];

    const int tid = threadIdx.x;
    const int lane = tid & 31, wid = tid >> 5;
    const int g = lane >> 2, t = lane & 3;
    const int wm = (wid & 1) << 6;
    const int wn = (wid >> 1) << 5;
    const int m0 = blockIdx.y * 128, n0 = blockIdx.x * 128;

    const int ar = tid >> 2, ak = (tid & 3) << 2;
    const int br = tid >> 5, bn = (tid & 31) << 2;

    const float* Ap = g_ctx + (size_t)(m0 + ar) * DM + ak;
    const float* Bp = W + (size_t)br * DM + n0 + bn;

    float acc[4][4][4] = {};
    float4 pa0, pa1, pb0, pb1;

    QKV_LDG(0);
    QKV_STS();
    __syncthreads();
    for (int k0 = 16; k0 < DM; k0 += 16) {
        QKV_LDG(k0);
        MMA_STEP(4, 4);
        __syncthreads();
        QKV_STS();
        __syncthreads();
    }
    MMA_STEP(4, 4);

    #pragma unroll
    for (int nt = 0; nt < 4; nt++) {
        int c = n0 + wn + nt*8 + 2*t;
        float2 bi = *(const float2*)(bias + c);
        #pragma unroll
        for (int mt = 0; mt < 4; mt++) {
            int r = m0 + wm + mt*16 + g;
            float2 r0 = *(const float2*)(resid + (size_t)r * DM + c);
            float2 r1 = *(const float2*)(resid + (size_t)(r+8) * DM + c);
            *(float2*)(g_x + (size_t)r * DM + c) =
                make_float2(acc[mt][nt][0] + bi.x + r0.x, acc[mt][nt][1] + bi.y + r0.y);
            *(float2*)(g_x + (size_t)(r+8) * DM + c) =
                make_float2(acc[mt][nt][2] + bi.x + r1.x, acc[mt][nt][3] + bi.y + r1.y);
        }
    }
}

// ===========================================================================
// Fused attention v6: SINGLE PASS with deferred normalization.
// Stores unnormalized exp to attn, accumulates rowsums + unnormalized P@V,
// then scales ctx and rescales the CTA's attn slice in a final sweep.
// 512 thr / 16 warps: 8 row-groups x 2 key-groups; fp16 fragments throughout.
// ===========================================================================
#define FA_QS   0
#define FA_KS   18432
#define FA_VH   55296
#define FA_RS   90112
#define FA_INV  91136
#define FA_SMEM 91648

__global__ void __launch_bounds__(512, 1) fused_attn_kernel(
    const unsigned char* __restrict__ mask, float* __restrict__ attn)
{
    extern __shared__ char smem[];
    unsigned (*Qs)[36]  = (unsigned(*)[36])(smem + FA_QS);   // half2 per elem
    unsigned (*Ks)[36]  = (unsigned(*)[36])(smem + FA_KS);   // 2 bufs x 128 rows
    unsigned (*Vhs)[68] = (unsigned(*)[68])(smem + FA_VH);   // 2 bufs x 64 d-rows
    float* rs   = (float*)(smem + FA_RS);    // [2][128]
    float* invp = (float*)(smem + FA_INV);   // [128]
    const unsigned sm_u = (unsigned)__cvta_generic_to_shared(smem);

    const int tid = threadIdx.x;
    const int lane = tid & 31, wid = tid >> 5;
    const int g = lane >> 2, t = lane & 3;
    const int wm = (wid & 7) << 4;     // q-row group: 16 rows each
    const int cg = wid >> 3;           // key-column group 0/1
    const int wn = cg << 6;            // key offset within tile: 0 or 64
    const int i0 = blockIdx.x * 128;
    const int bh = blockIdx.y;
    const int b = bh >> 4, h = bh & 15;

    const half* qbase = g_qh + ((size_t)bh * SEQ + i0) * DHEAD;
    const half* kbase = g_kh + (size_t)bh * SEQ * DHEAD;
    const half* vhbase = g_vh + (size_t)bh * DHEAD * SEQ;
    const unsigned char* mbase = mask + (size_t)b * SEQ * SEQ;
    float* abase = attn + (size_t)bh * SEQ * SEQ;

    // Q tile (128 x 64 fp16 = 16KB)
    #pragma unroll
    for (int c = 0; c < 2; c++) {
        int idx = tid + c * 512;
        int j = idx >> 3, ch = idx & 7;
        CPA16(sm_u + FA_QS + (j*36 + ch*4)*4, qbase + (size_t)j * DHEAD + ch*8);
    }
    CP_COMMIT();

    #define ISSUE_K(jt, bb) do { \
        _Pragma("unroll") \
        for (int c = 0; c < 2; c++) { \
            int idx = tid + c * 512; \
            int j = idx >> 3, ch = idx & 7; \
            CPA16(sm_u + FA_KS + (((bb)*128 + j)*36 + ch*4)*4, \
                  kbase + (size_t)((jt)*128 + j) * DHEAD + ch*8); \
        } } while(0)
    #define ISSUE_V(jt, bb) do { \
        _Pragma("unroll") \
        for (int c = 0; c < 2; c++) { \
            int idx = tid + c * 512; \
            int d = idx >> 4, ch = idx & 15; \
            CPA16(sm_u + FA_VH + (((bb)*64 + d)*68 + ch*4)*4, \
                  vhbase + (size_t)d * SEQ + (jt)*128 + ch*8); \
        } } while(0)

    // score mma: fp16 m16n8k16, warp tile 16m x 64n
    #define FA_SMMA(Kb) do { \
        _Pragma("unroll") \
        for (int kh = 0; kh < 32; kh += 8) { \
            unsigned a0 = Qs[wm+g][kh+t],   a1 = Qs[wm+g+8][kh+t]; \
            unsigned a2 = Qs[wm+g][kh+t+4], a3 = Qs[wm+g+8][kh+t+4]; \
            _Pragma("unroll") \
            for (int nt = 0; nt < 8; nt++) { \
                unsigned b0 = (Kb)[wn+nt*8+g][kh+t]; \
                unsigned b1 = (Kb)[wn+nt*8+g][kh+t+4]; \
                MMA16816(acc[nt], a0, a1, a2, a3, b0, b1); \
            } \
        } } while(0)

    ISSUE_K(0, 0);
    ISSUE_V(0, 0);
    CP_COMMIT();

    const float scale = 0.125f;
    float p0 = 0.f, p1 = 0.f;
    float cacc[8][4] = {};

    // ---------------- SINGLE PASS: exp + attn(unnorm) + rowsum + P@V -------
    for (int jt = 0; jt < 16; jt++) {
        if (jt < 15) { ISSUE_K(jt+1, (jt+1)&1); ISSUE_V(jt+1, (jt+1)&1); }
        CP_COMMIT();
        CP_WAIT1();
        __syncthreads();
        unsigned (*Kb)[36] = Ks + (jt&1)*128;
        unsigned (*Vb)[68] = Vhs + (jt&1)*64;
        float acc[8][4] = {};
        FA_SMMA(Kb);
        int j0 = jt * 128;
        #pragma unroll
        for (int nt = 0; nt < 8; nt++) {
            int cgc = j0 + wn + nt*8 + 2*t;
            int r0 = i0 + wm + g;
            uchar2 m0v = *(const uchar2*)(mbase + (size_t)r0 * SEQ + cgc);
            uchar2 m1v = *(const uchar2*)(mbase + (size_t)(r0+8) * SEQ + cgc);
            float e0 = __expf(m0v.x ? -60.f : acc[nt][0]*scale);
            float e1 = __expf(m0v.y ? -60.f : acc[nt][1]*scale);
            float e2 = __expf(m1v.x ? -60.f : acc[nt][2]*scale);
            float e3 = __expf(m1v.y ? -60.f : acc[nt][3]*scale);
            p0 += e0 + e1;
            p1 += e2 + e3;
            *(float2*)(abase + (size_t)r0 * SEQ + cgc)     = make_float2(e0, e1);
            *(float2*)(abase + (size_t)(r0+8) * SEQ + cgc) = make_float2(e2, e3);
            acc[nt][0] = e0; acc[nt][1] = e1; acc[nt][2] = e2; acc[nt][3] = e3;
        }
        // ctx: cacc += P(16 x 64keys) @ V(64keys x 64d), unnormalized
        #pragma unroll
        for (int kb = 0; kb < 4; kb++) {
            unsigned a0 = h2pack(acc[2*kb][0],   acc[2*kb][1]);
            unsigned a1 = h2pack(acc[2*kb][2],   acc[2*kb][3]);
            unsigned a2 = h2pack(acc[2*kb+1][0], acc[2*kb+1][1]);
            unsigned a3 = h2pack(acc[2*kb+1][2], acc[2*kb+1][3]);
            int jp = (wn >> 1) + kb*8 + t;
            #pragma unroll
            for (int nn = 0; nn < 8; nn++) {
                int d = nn*8 + g;
                unsigned b0 = Vb[d][jp];
                unsigned b1 = Vb[d][jp + 4];
                MMA16816(cacc[nn], a0, a1, a2, a3, b0, b1);
            }
        }
        __syncthreads();
    }

    // rowsum reduce: 4 lanes/row, then 2 key-groups via smem
    p0 += __shfl_xor_sync(0xffffffffu, p0, 1);
    p0 += __shfl_xor_sync(0xffffffffu, p0, 2);
    p1 += __shfl_xor_sync(0xffffffffu, p1, 1);
    p1 += __shfl_xor_sync(0xffffffffu, p1, 2);
    if (t == 0) {
        rs[cg*128 + wm + g]     = p0;
        rs[cg*128 + wm + g + 8] = p1;
    }
    __syncthreads();
    if (tid < 128) invp[tid] = 1.0f / (rs[tid] + rs[128 + tid]);
    __syncthreads();

    const float iv0 = invp[wm + g];
    const float iv1 = invp[wm + g + 8];

    // ctx: 2-way reduce K-split partials, scale by invp, write g_ctx
    float (*red)[68] = (float(*)[68])(smem + FA_KS);
    if (cg == 1) {
        #pragma unroll
        for (int nn = 0; nn < 8; nn++) {
            red[wm+g][nn*8+2*t]     = cacc[nn][0];
            red[wm+g][nn*8+2*t+1]   = cacc[nn][1];
            red[wm+g+8][nn*8+2*t]   = cacc[nn][2];
            red[wm+g+8][nn*8+2*t+1] = cacc[nn][3];
        }
    }
    __syncthreads();
    if (cg == 0) {
        #pragma unroll
        for (int nn = 0; nn < 8; nn++) {
            int d = nn*8 + 2*t;
            int r = i0 + wm + g;
            size_t tok = (size_t)b * SEQ + r;
            *(float2*)(g_ctx + tok * DM + h*DHEAD + d) =
                make_float2((cacc[nn][0] + red[wm+g][d])   * iv0,
                            (cacc[nn][1] + red[wm+g][d+1]) * iv0);
            *(float2*)(g_ctx + (tok+8) * DM + h*DHEAD + d) =
                make_float2((cacc[nn][2] + red[wm+g+8][d])   * iv1,
                            (cacc[nn][3] + red[wm+g+8][d+1]) * iv1);
        }
    }

    // ---------------- rescale attn slice: attn *= invp[row] ----------------
    // 128 rows x 2048 cols = 65536 float4; 128 per thread, coalesced.
    #pragma unroll 4
    for (int it = 0; it < 128; it++) {
        int idx = it * 512 + tid;
        int row = idx >> 9;           // 0..127 (warp-uniform)
        int c4  = idx & 511;
        float iv = invp[row];
        float* p = abase + (size_t)(i0 + row) * SEQ + c4 * 4;
        float4 v = *(float4*)p;
        v.x *= iv; v.y *= iv; v.z *= iv; v.w *= iv;
        *(float4*)p = v;
    }
}

// ===========================================================================
// LayerNorm over g_x rows -> out region of d_out.
// ===========================================================================
__global__ void __launch_bounds__(256) ln_kernel(
    const float* __restrict__ gamma, const float* __restrict__ beta,
    float* __restrict__ out)
{
    const int tk = blockIdx.x;
    const int tid = threadIdx.x;
    float4 v = *(const float4*)(g_x + (size_t)tk * DM + (tid << 2));
    float s  = v.x + v.y + v.z + v.w;
    float ss = v.x*v.x + v.y*v.y + v.z*v.z + v.w*v.w;

    __shared__ float r1[8], r2[8];
    #pragma unroll
    for (int o = 16; o; o >>= 1) {
        s  += __shfl_xor_sync(0xffffffffu, s, o);
        ss += __shfl_xor_sync(0xffffffffu, ss, o);
    }
    if ((tid & 31) == 0) { r1[tid >> 5] = s; r2[tid >> 5] = ss; }
    __syncthreads();
    float ts = 0.f, tss = 0.f;
    #pragma unroll
    for (int w = 0; w < 8; w++) { ts += r1[w]; tss += r2[w]; }

    float mu  = ts * (1.0f / DM);
    float var = tss * (1.0f / DM) - mu * mu;
    float inv = rsqrtf(var + LN_EPS);

    float4 ga = *(const float4*)(gamma + (tid << 2));
    float4 be = *(const float4*)(beta  + (tid << 2));
    float4 o;
    o.x = (v.x - mu) * inv * ga.x + be.x;
    o.y = (v.y - mu) * inv * ga.y + be.y;
    o.z = (v.z - mu) * inv * ga.z + be.z;
    o.w = (v.w - mu) * inv * ga.w + be.w;
    *(float4*)(out + (size_t)tk * DM + (tid << 2)) = o;
}

// ===========================================================================
extern "C" void kernel_launch(void* const* d_in, const int* in_sizes, int n_in,
                              void* d_out, int out_size)
{
    const float* Q  = (const float*)d_in[0];
    const float* K  = (const float*)d_in[1];
    const float* V  = (const float*)d_in[2];
    const unsigned char* mask = (const unsigned char*)d_in[3];
    const float* Wq = (const float*)d_in[4];
    const float* bq = (const float*)d_in[5];
    const float* Wk = (const float*)d_in[6];
    const float* bk = (const float*)d_in[7];
    const float* Wv = (const float*)d_in[8];
    const float* bv = (const float*)d_in[9];
    const float* Wo = (const float*)d_in[10];
    const float* bo = (const float*)d_in[11];
    const float* gamma = (const float*)d_in[12];
    const float* beta  = (const float*)d_in[13];

    float* out  = (float*)d_out;
    float* attn = out + ATTN_OFF;

    cudaFuncSetAttribute(fused_attn_kernel,
                         cudaFuncAttributeMaxDynamicSharedMemorySize, FA_SMEM);

    qkv_kernel<<<dim3(DM/128, TTOK/128, 3), 256>>>(Q, K, V, Wq, Wk, Wv, bq, bk, bv);
    fused_attn_kernel<<<dim3(SEQ/128, BHN), 512, FA_SMEM>>>(mask, attn);
    oproj_kernel<<<dim3(DM/128, TTOK/128), 256>>>(Wo, bo, Q);
    ln_kernel<<<TTOK, 256>>>(gamma, beta, out);
}

// round 13
// speedup vs baseline: 1.2334x; 1.2334x over previous
#include <cuda_runtime.h>
#include <cuda_fp16.h>
#include <math.h>

#define BATCH 2
#define SEQ   2048
#define NH    16
#define DHEAD 64
#define DM    1024
#define TTOK  (BATCH*SEQ)
#define BHN   (BATCH*NH)
#define ATTN_OFF ((size_t)BATCH*SEQ*DM)
#define LN_EPS 1e-5f

__device__ half  g_qh[(size_t)BHN*SEQ*DHEAD];    // [B,H,S,64] fp16
__device__ half  g_kh[(size_t)BHN*SEQ*DHEAD];    // [B,H,S,64] fp16
__device__ half  g_vh[(size_t)BHN*DHEAD*SEQ];    // [B,H,64,S] fp16 transposed
__device__ float g_ctx[(size_t)TTOK*DM];          // [T, H*64]
__device__ float g_x[(size_t)TTOK*DM];            // pre-LN

__device__ __forceinline__ unsigned tf32(float f) {
    unsigned u;
    asm("cvt.rna.tf32.f32 %0, %1;" : "=r"(u) : "f"(f));
    return u;
}
__device__ __forceinline__ unsigned h2pack(float x, float y) {
    __half2 h = __floats2half2_rn(x, y);
    return *(unsigned*)&h;
}

#define MMA(d, a, b) \
    asm volatile("mma.sync.aligned.m16n8k8.row.col.f32.tf32.tf32.f32 " \
        "{%0,%1,%2,%3}, {%4,%5,%6,%7}, {%8,%9}, {%0,%1,%2,%3};" \
        : "+f"((d)[0]), "+f"((d)[1]), "+f"((d)[2]), "+f"((d)[3]) \
        : "r"((a)[0]), "r"((a)[1]), "r"((a)[2]), "r"((a)[3]), \
          "r"((b)[0]), "r"((b)[1]))

#define MMA16816(d, a0,a1,a2,a3, b0,b1) \
    asm volatile("mma.sync.aligned.m16n8k16.row.col.f32.f16.f16.f32 " \
        "{%0,%1,%2,%3}, {%4,%5,%6,%7}, {%8,%9}, {%0,%1,%2,%3};" \
        : "+f"((d)[0]), "+f"((d)[1]), "+f"((d)[2]), "+f"((d)[3]) \
        : "r"(a0), "r"(a1), "r"(a2), "r"(a3), "r"(b0), "r"(b1))

#define CPA16(dst, src) \
    asm volatile("cp.async.ca.shared.global [%0], [%1], 16;\n" \
        :: "r"((unsigned)(dst)), "l"((const void*)(src)))
#define CP_COMMIT() asm volatile("cp.async.commit_group;\n")
#define CP_WAIT1()  asm volatile("cp.async.wait_group 1;\n")

// One K=16 chunk of mma work for the projection kernels (As/Bs chunked).
#define MMA_STEP(NMT, NNT) \
    _Pragma("unroll") \
    for (int kk = 0; kk < 16; kk += 8) { \
        unsigned af[NMT][4]; unsigned bf[NNT][2]; \
        _Pragma("unroll") \
        for (int mt = 0; mt < NMT; mt++) { \
            int mr = wm + mt*16 + g; \
            af[mt][0] = As[mr][kk+t];   af[mt][1] = As[mr+8][kk+t]; \
            af[mt][2] = As[mr][kk+t+4]; af[mt][3] = As[mr+8][kk+t+4]; \
        } \
        _Pragma("unroll") \
        for (int nt = 0; nt < NNT; nt++) { \
            bf[nt][0] = Bs[kk+t][wn + nt*8 + g]; \
            bf[nt][1] = Bs[kk+t+4][wn + nt*8 + g]; \
        } \
        _Pragma("unroll") \
        for (int mt = 0; mt < NMT; mt++) \
            _Pragma("unroll") \
            for (int nt = 0; nt < NNT; nt++) \
                MMA(acc[mt][nt], af[mt], bf[nt]); \
    }

// ===========================================================================
// QKV projection (tf32 mma). Q/K: fp16 [B,H,S,64]. V: fp16 [B,H,64,S].
// ===========================================================================
__global__ void __launch_bounds__(256) qkv_kernel(
    const float* __restrict__ Qin, const float* __restrict__ Kin,
    const float* __restrict__ Vin,
    const float* __restrict__ Wq, const float* __restrict__ Wk,
    const float* __restrict__ Wv,
    const float* __restrict__ bq, const float* __restrict__ bk,
    const float* __restrict__ bv)
{
    __shared__ unsigned As[128][20];
    __shared__ unsigned Bs[16][136];

    const int z = blockIdx.z;
    const float* X    = (z == 0) ? Qin : (z == 1) ? Kin : Vin;
    const float* W    = (z == 0) ? Wq  : (z == 1) ? Wk  : Wv;
    const float* bias = (z == 0) ? bq  : (z == 1) ? bk  : bv;

    const int tid = threadIdx.x;
    const int lane = tid & 31, wid = tid >> 5;
    const int g = lane >> 2, t = lane & 3;
    const int wm = (wid & 1) << 6;
    const int wn = (wid >> 1) << 5;
    const int m0 = blockIdx.y * 128, n0 = blockIdx.x * 128;

    const int ar = tid >> 2, ak = (tid & 3) << 2;
    const int br = tid >> 5, bn = (tid & 31) << 2;

    const float* Ap = X + (size_t)(m0 + ar) * DM + ak;
    const float* Bp = W + (size_t)br * DM + n0 + bn;

    float acc[4][4][4] = {};
    float4 pa0, pa1, pb0, pb1;

    #define QKV_LDG(k0) do { \
        pa0 = *(const float4*)(Ap + (k0)); \
        pa1 = *(const float4*)(Ap + (size_t)64 * DM + (k0)); \
        pb0 = *(const float4*)(Bp + (size_t)(k0) * DM); \
        pb1 = *(const float4*)(Bp + (size_t)((k0) + 8) * DM); } while(0)

    #define QKV_STS() do { \
        *(uint4*)&As[ar][ak]    = make_uint4(tf32(pa0.x), tf32(pa0.y), tf32(pa0.z), tf32(pa0.w)); \
        *(uint4*)&As[ar+64][ak] = make_uint4(tf32(pa1.x), tf32(pa1.y), tf32(pa1.z), tf32(pa1.w)); \
        *(uint4*)&Bs[br][bn]    = make_uint4(tf32(pb0.x), tf32(pb0.y), tf32(pb0.z), tf32(pb0.w)); \
        *(uint4*)&Bs[br+8][bn]  = make_uint4(tf32(pb1.x), tf32(pb1.y), tf32(pb1.z), tf32(pb1.w)); } while(0)

    QKV_LDG(0);
    QKV_STS();
    __syncthreads();
    for (int k0 = 16; k0 < DM; k0 += 16) {
        QKV_LDG(k0);
        MMA_STEP(4, 4);
        __syncthreads();
        QKV_STS();
        __syncthreads();
    }
    MMA_STEP(4, 4);

    #pragma unroll
    for (int nt = 0; nt < 4; nt++) {
        int c = n0 + wn + nt*8 + 2*t;
        int h = c >> 6, d = c & 63;
        float2 bi = *(const float2*)(bias + c);
        #pragma unroll
        for (int mt = 0; mt < 4; mt++) {
            int r = m0 + wm + mt*16 + g;
            int b = r >> 11, s = r & (SEQ - 1);
            int bh = b * NH + h;
            float v0 = acc[mt][nt][0] + bi.x;
            float v1 = acc[mt][nt][1] + bi.y;
            float v2 = acc[mt][nt][2] + bi.x;
            float v3 = acc[mt][nt][3] + bi.y;
            if (z == 2) {
                half* vb = g_vh + ((size_t)bh * DHEAD + d) * SEQ;
                vb[s]          = __float2half(v0);
                vb[SEQ + s]    = __float2half(v1);
                vb[s + 8]      = __float2half(v2);
                vb[SEQ + s + 8]= __float2half(v3);
            } else {
                half* out = (z == 0) ? g_qh : g_kh;
                half* op = out + ((size_t)bh * SEQ + s) * DHEAD + d;
                *(unsigned*)op = h2pack(v0, v1);
                op += (size_t)8 * DHEAD;
                *(unsigned*)op = h2pack(v2, v3);
            }
        }
    }
}

// ===========================================================================
// Output projection (tf32 mma): g_x = g_ctx @ Wo + bo + residual.
// ===========================================================================
__global__ void __launch_bounds__(256) oproj_kernel(
    const float* __restrict__ W, const float* __restrict__ bias,
    const float* __restrict__ resid)
{
    __shared__ unsigned As[128][20];
    __shared__ unsigned Bs[16][136];

    const int tid = threadIdx.x;
    const int lane = tid & 31, wid = tid >> 5;
    const int g = lane >> 2, t = lane & 3;
    const int wm = (wid & 1) << 6;
    const int wn = (wid >> 1) << 5;
    const int m0 = blockIdx.y * 128, n0 = blockIdx.x * 128;

    const int ar = tid >> 2, ak = (tid & 3) << 2;
    const int br = tid >> 5, bn = (tid & 31) << 2;

    const float* Ap = g_ctx + (size_t)(m0 + ar) * DM + ak;
    const float* Bp = W + (size_t)br * DM + n0 + bn;

    float acc[4][4][4] = {};
    float4 pa0, pa1, pb0, pb1;

    QKV_LDG(0);
    QKV_STS();
    __syncthreads();
    for (int k0 = 16; k0 < DM; k0 += 16) {
        QKV_LDG(k0);
        MMA_STEP(4, 4);
        __syncthreads();
        QKV_STS();
        __syncthreads();
    }
    MMA_STEP(4, 4);

    #pragma unroll
    for (int nt = 0; nt < 4; nt++) {
        int c = n0 + wn + nt*8 + 2*t;
        float2 bi = *(const float2*)(bias + c);
        #pragma unroll
        for (int mt = 0; mt < 4; mt++) {
            int r = m0 + wm + mt*16 + g;
            float2 r0 = *(const float2*)(resid + (size_t)r * DM + c);
            float2 r1 = *(const float2*)(resid + (size_t)(r+8) * DM + c);
            *(float2*)(g_x + (size_t)r * DM + c) =
                make_float2(acc[mt][nt][0] + bi.x + r0.x, acc[mt][nt][1] + bi.y + r0.y);
            *(float2*)(g_x + (size_t)(r+8) * DM + c) =
                make_float2(acc[mt][nt][2] + bi.x + r1.x, acc[mt][nt][3] + bi.y + r1.y);
        }
    }
}

// ===========================================================================
// Fused attention v7: two-pass (R11 structure) at 2 CTAs/SM.
// 256 thr / 8 warps per CTA: 4 row-groups (16 q-rows) x 2 key-groups.
// CTA covers 64 q-rows; grid (SEQ/64, BHN). Smem ~80KB -> 2 CTAs/SM.
// ===========================================================================
#define FA_QS   0
#define FA_KS   9216
#define FA_VH   46080
#define FA_RS   80896
#define FA_INV  81408
#define FA_SMEM 81664

__global__ void __launch_bounds__(256, 2) fused_attn_kernel(
    const unsigned char* __restrict__ mask, float* __restrict__ attn)
{
    extern __shared__ char smem[];
    unsigned (*Qs)[36]  = (unsigned(*)[36])(smem + FA_QS);   // 64 rows, half2
    unsigned (*Ks)[36]  = (unsigned(*)[36])(smem + FA_KS);   // 2 bufs x 128 rows
    unsigned (*Vhs)[68] = (unsigned(*)[68])(smem + FA_VH);   // 2 bufs x 64 d-rows
    float* rs   = (float*)(smem + FA_RS);    // [2][64]
    float* invp = (float*)(smem + FA_INV);   // [64]
    const unsigned sm_u = (unsigned)__cvta_generic_to_shared(smem);

    const int tid = threadIdx.x;
    const int lane = tid & 31, wid = tid >> 5;
    const int g = lane >> 2, t = lane & 3;
    const int wm = (wid & 3) << 4;     // q-row group: 0,16,32,48
    const int cg = wid >> 2;           // key-column group 0/1
    const int wn = cg << 6;            // key offset within tile: 0 or 64
    const int i0 = blockIdx.x * 64;
    const int bh = blockIdx.y;
    const int b = bh >> 4, h = bh & 15;

    const half* qbase = g_qh + ((size_t)bh * SEQ + i0) * DHEAD;
    const half* kbase = g_kh + (size_t)bh * SEQ * DHEAD;
    const half* vhbase = g_vh + (size_t)bh * DHEAD * SEQ;
    const unsigned char* mbase = mask + (size_t)b * SEQ * SEQ;
    float* abase = attn + (size_t)bh * SEQ * SEQ;

    // Q tile (64 x 64 fp16 = 8KB): 512 chunks of 16B, 2 per thread
    #pragma unroll
    for (int c = 0; c < 2; c++) {
        int idx = tid + c * 256;
        int j = idx >> 3, ch = idx & 7;
        CPA16(sm_u + FA_QS + (j*36 + ch*4)*4, qbase + (size_t)j * DHEAD + ch*8);
    }
    CP_COMMIT();

    #define ISSUE_K(jt, bb) do { \
        _Pragma("unroll") \
        for (int c = 0; c < 4; c++) { \
            int idx = tid + c * 256; \
            int j = idx >> 3, ch = idx & 7; \
            CPA16(sm_u + FA_KS + (((bb)*128 + j)*36 + ch*4)*4, \
                  kbase + (size_t)((jt)*128 + j) * DHEAD + ch*8); \
        } } while(0)
    #define ISSUE_V(jt, bb) do { \
        _Pragma("unroll") \
        for (int c = 0; c < 4; c++) { \
            int idx = tid + c * 256; \
            int d = idx >> 4, ch = idx & 15; \
            CPA16(sm_u + FA_VH + (((bb)*64 + d)*68 + ch*4)*4, \
                  vhbase + (size_t)d * SEQ + (jt)*128 + ch*8); \
        } } while(0)

    // score mma: fp16 m16n8k16, warp tile 16m x 64n
    #define FA_SMMA(Kb) do { \
        _Pragma("unroll") \
        for (int kh = 0; kh < 32; kh += 8) { \
            unsigned a0 = Qs[wm+g][kh+t],   a1 = Qs[wm+g+8][kh+t]; \
            unsigned a2 = Qs[wm+g][kh+t+4], a3 = Qs[wm+g+8][kh+t+4]; \
            _Pragma("unroll") \
            for (int nt = 0; nt < 8; nt++) { \
                unsigned b0 = (Kb)[wn+nt*8+g][kh+t]; \
                unsigned b1 = (Kb)[wn+nt*8+g][kh+t+4]; \
                MMA16816(acc[nt], a0, a1, a2, a3, b0, b1); \
            } \
        } } while(0)

    ISSUE_K(0, 0);
    CP_COMMIT();

    const float scale = 0.125f;
    float p0 = 0.f, p1 = 0.f;

    // ---------------- PASS A: row sums ----------------
    for (int jt = 0; jt < 16; jt++) {
        if (jt < 15) ISSUE_K(jt+1, (jt+1)&1);
        CP_COMMIT();
        CP_WAIT1();
        __syncthreads();
        unsigned (*Kb)[36] = Ks + (jt&1)*128;
        float acc[8][4] = {};
        FA_SMMA(Kb);
        int j0 = jt * 128;
        #pragma unroll
        for (int nt = 0; nt < 8; nt++) {
            int cgc = j0 + wn + nt*8 + 2*t;
            int r0 = i0 + wm + g;
            uchar2 m0v = *(const uchar2*)(mbase + (size_t)r0 * SEQ + cgc);
            uchar2 m1v = *(const uchar2*)(mbase + (size_t)(r0+8) * SEQ + cgc);
            p0 += __expf(m0v.x ? -60.f : acc[nt][0]*scale)
                + __expf(m0v.y ? -60.f : acc[nt][1]*scale);
            p1 += __expf(m1v.x ? -60.f : acc[nt][2]*scale)
                + __expf(m1v.y ? -60.f : acc[nt][3]*scale);
        }
        __syncthreads();
    }

    // rowsum reduce: 4 lanes/row, then 2 key-groups via smem
    p0 += __shfl_xor_sync(0xffffffffu, p0, 1);
    p0 += __shfl_xor_sync(0xffffffffu, p0, 2);
    p1 += __shfl_xor_sync(0xffffffffu, p1, 1);
    p1 += __shfl_xor_sync(0xffffffffu, p1, 2);
    if (t == 0) {
        rs[cg*64 + wm + g]     = p0;
        rs[cg*64 + wm + g + 8] = p1;
    }
    __syncthreads();
    if (tid < 64) invp[tid] = 1.0f / (rs[tid] + rs[64 + tid]);

    ISSUE_K(0, 0);
    ISSUE_V(0, 0);
    CP_COMMIT();
    __syncthreads();   // invp visible

    const float iv0 = invp[wm + g];
    const float iv1 = invp[wm + g + 8];

    // ---------------- PASS B: emit attn + register-path P@V ----------------
    float cacc[8][4] = {};
    for (int jt = 0; jt < 16; jt++) {
        if (jt < 15) { ISSUE_K(jt+1, (jt+1)&1); ISSUE_V(jt+1, (jt+1)&1); }
        CP_COMMIT();
        CP_WAIT1();
        __syncthreads();
        unsigned (*Kb)[36] = Ks + (jt&1)*128;
        unsigned (*Vb)[68] = Vhs + (jt&1)*64;
        float acc[8][4] = {};
        FA_SMMA(Kb);
        int j0 = jt * 128;
        #pragma unroll
        for (int nt = 0; nt < 8; nt++) {
            int cgc = j0 + wn + nt*8 + 2*t;
            int r0 = i0 + wm + g;
            uchar2 m0v = *(const uchar2*)(mbase + (size_t)r0 * SEQ + cgc);
            uchar2 m1v = *(const uchar2*)(mbase + (size_t)(r0+8) * SEQ + cgc);
            float e0 = __expf(m0v.x ? -60.f : acc[nt][0]*scale) * iv0;
            float e1 = __expf(m0v.y ? -60.f : acc[nt][1]*scale) * iv0;
            float e2 = __expf(m1v.x ? -60.f : acc[nt][2]*scale) * iv1;
            float e3 = __expf(m1v.y ? -60.f : acc[nt][3]*scale) * iv1;
            *(float2*)(abase + (size_t)r0 * SEQ + cgc)     = make_float2(e0, e1);
            *(float2*)(abase + (size_t)(r0+8) * SEQ + cgc) = make_float2(e2, e3);
            acc[nt][0] = e0; acc[nt][1] = e1; acc[nt][2] = e2; acc[nt][3] = e3;
        }
        // ctx: cacc += P(16 x 64keys) @ V(64keys x 64d); B frags ready half2
        #pragma unroll
        for (int kb = 0; kb < 4; kb++) {
            unsigned a0 = h2pack(acc[2*kb][0],   acc[2*kb][1]);
            unsigned a1 = h2pack(acc[2*kb][2],   acc[2*kb][3]);
            unsigned a2 = h2pack(acc[2*kb+1][0], acc[2*kb+1][1]);
            unsigned a3 = h2pack(acc[2*kb+1][2], acc[2*kb+1][3]);
            int jp = (wn >> 1) + kb*8 + t;
            #pragma unroll
            for (int nn = 0; nn < 8; nn++) {
                int d = nn*8 + g;
                unsigned b0 = Vb[d][jp];
                unsigned b1 = Vb[d][jp + 4];
                MMA16816(cacc[nn], a0, a1, a2, a3, b0, b1);
            }
        }
        __syncthreads();
    }

    // 2-way reduction of K-split context partials, then write g_ctx
    float (*red)[68] = (float(*)[68])(smem + FA_KS);
    if (cg == 1) {
        #pragma unroll
        for (int nn = 0; nn < 8; nn++) {
            red[wm+g][nn*8+2*t]     = cacc[nn][0];
            red[wm+g][nn*8+2*t+1]   = cacc[nn][1];
            red[wm+g+8][nn*8+2*t]   = cacc[nn][2];
            red[wm+g+8][nn*8+2*t+1] = cacc[nn][3];
        }
    }
    __syncthreads();
    if (cg == 0) {
        #pragma unroll
        for (int nn = 0; nn < 8; nn++) {
            int d = nn*8 + 2*t;
            int r = i0 + wm + g;
            size_t tok = (size_t)b * SEQ + r;
            *(float2*)(g_ctx + tok * DM + h*DHEAD + d) =
                make_float2(cacc[nn][0] + red[wm+g][d], cacc[nn][1] + red[wm+g][d+1]);
            *(float2*)(g_ctx + (tok+8) * DM + h*DHEAD + d) =
                make_float2(cacc[nn][2] + red[wm+g+8][d], cacc[nn][3] + red[wm+g+8][d+1]);
        }
    }
}

// ===========================================================================
// LayerNorm over g_x rows -> out region of d_out.
// ===========================================================================
__global__ void __launch_bounds__(256) ln_kernel(
    const float* __restrict__ gamma, const float* __restrict__ beta,
    float* __restrict__ out)
{
    const int tk = blockIdx.x;
    const int tid = threadIdx.x;
    float4 v = *(const float4*)(g_x + (size_t)tk * DM + (tid << 2));
    float s  = v.x + v.y + v.z + v.w;
    float ss = v.x*v.x + v.y*v.y + v.z*v.z + v.w*v.w;

    __shared__ float r1[8], r2[8];
    #pragma unroll
    for (int o = 16; o; o >>= 1) {
        s  += __shfl_xor_sync(0xffffffffu, s, o);
        ss += __shfl_xor_sync(0xffffffffu, ss, o);
    }
    if ((tid & 31) == 0) { r1[tid >> 5] = s; r2[tid >> 5] = ss; }
    __syncthreads();
    float ts = 0.f, tss = 0.f;
    #pragma unroll
    for (int w = 0; w < 8; w++) { ts += r1[w]; tss += r2[w]; }

    float mu  = ts * (1.0f / DM);
    float var = tss * (1.0f / DM) - mu * mu;
    float inv = rsqrtf(var + LN_EPS);

    float4 ga = *(const float4*)(gamma + (tid << 2));
    float4 be = *(const float4*)(beta  + (tid << 2));
    float4 o;
    o.x = (v.x - mu) * inv * ga.x + be.x;
    o.y = (v.y - mu) * inv * ga.y + be.y;
    o.z = (v.z - mu) * inv * ga.z + be.z;
    o.w = (v.w - mu) * inv * ga.w + be.w;
    *(float4*)(out + (size_t)tk * DM + (tid << 2)) = o;
}

// ===========================================================================
extern "C" void kernel_launch(void* const* d_in, const int* in_sizes, int n_in,
                              void* d_out, int out_size)
{
    const float* Q  = (const float*)d_in[0];
    const float* K  = (const float*)d_in[1];
    const float* V  = (const float*)d_in[2];
    const unsigned char* mask = (const unsigned char*)d_in[3];
    const float* Wq = (const float*)d_in[4];
    const float* bq = (const float*)d_in[5];
    const float* Wk = (const float*)d_in[6];
    const float* bk = (const float*)d_in[7];
    const float* Wv = (const float*)d_in[8];
    const float* bv = (const float*)d_in[9];
    const float* Wo = (const float*)d_in[10];
    const float* bo = (const float*)d_in[11];
    const float* gamma = (const float*)d_in[12];
    const float* beta  = (const float*)d_in[13];

    float* out  = (float*)d_out;
    float* attn = out + ATTN_OFF;

    cudaFuncSetAttribute(fused_attn_kernel,
                         cudaFuncAttributeMaxDynamicSharedMemorySize, FA_SMEM);

    qkv_kernel<<<dim3(DM/128, TTOK/128, 3), 256>>>(Q, K, V, Wq, Wk, Wv, bq, bk, bv);
    fused_attn_kernel<<<dim3(SEQ/64, BHN), 256, FA_SMEM>>>(mask, attn);
    oproj_kernel<<<dim3(DM/128, TTOK/128), 256>>>(Wo, bo, Q);
    ln_kernel<<<TTOK, 256>>>(gamma, beta, out);
}

// round 14
// speedup vs baseline: 1.2618x; 1.0230x over previous
#include <cuda_runtime.h>
#include <cuda_fp16.h>
#include <math.h>

#define BATCH 2
#define SEQ   2048
#define NH    16
#define DHEAD 64
#define DM    1024
#define TTOK  (BATCH*SEQ)
#define BHN   (BATCH*NH)
#define ATTN_OFF ((size_t)BATCH*SEQ*DM)
#define LN_EPS 1e-5f

__device__ half  g_qh[(size_t)BHN*SEQ*DHEAD];    // [B,H,S,64] fp16
__device__ half  g_kh[(size_t)BHN*SEQ*DHEAD];    // [B,H,S,64] fp16
__device__ half  g_vh[(size_t)BHN*DHEAD*SEQ];    // [B,H,64,S] fp16 transposed
__device__ float g_ctx[(size_t)TTOK*DM];          // [T, H*64]
__device__ float g_x[(size_t)TTOK*DM];            // pre-LN

__device__ __forceinline__ unsigned tf32(float f) {
    unsigned u;
    asm("cvt.rna.tf32.f32 %0, %1;" : "=r"(u) : "f"(f));
    return u;
}
__device__ __forceinline__ unsigned h2pack(float x, float y) {
    __half2 h = __floats2half2_rn(x, y);
    return *(unsigned*)&h;
}

#define MMA(d, a, b) \
    asm volatile("mma.sync.aligned.m16n8k8.row.col.f32.tf32.tf32.f32 " \
        "{%0,%1,%2,%3}, {%4,%5,%6,%7}, {%8,%9}, {%0,%1,%2,%3};" \
        : "+f"((d)[0]), "+f"((d)[1]), "+f"((d)[2]), "+f"((d)[3]) \
        : "r"((a)[0]), "r"((a)[1]), "r"((a)[2]), "r"((a)[3]), \
          "r"((b)[0]), "r"((b)[1]))

#define MMA16816(d, a0,a1,a2,a3, b0,b1) \
    asm volatile("mma.sync.aligned.m16n8k16.row.col.f32.f16.f16.f32 " \
        "{%0,%1,%2,%3}, {%4,%5,%6,%7}, {%8,%9}, {%0,%1,%2,%3};" \
        : "+f"((d)[0]), "+f"((d)[1]), "+f"((d)[2]), "+f"((d)[3]) \
        : "r"(a0), "r"(a1), "r"(a2), "r"(a3), "r"(b0), "r"(b1))

#define LDSM_X4(r0,r1,r2,r3, addr) \
    asm volatile("ldmatrix.sync.aligned.m8n8.x4.shared.b16 {%0,%1,%2,%3}, [%4];" \
        : "=r"(r0), "=r"(r1), "=r"(r2), "=r"(r3) : "r"(addr))
#define LDSM_X2(r0,r1, addr) \
    asm volatile("ldmatrix.sync.aligned.m8n8.x2.shared.b16 {%0,%1}, [%2];" \
        : "=r"(r0), "=r"(r1) : "r"(addr))

#define CPA16(dst, src) \
    asm volatile("cp.async.ca.shared.global [%0], [%1], 16;\n" \
        :: "r"((unsigned)(dst)), "l"((const void*)(src)))
#define CP_COMMIT() asm volatile("cp.async.commit_group;\n")
#define CP_WAIT1()  asm volatile("cp.async.wait_group 1;\n")

// One K=16 chunk of mma work for the projection kernels (As/Bs chunked).
#define MMA_STEP(NMT, NNT) \
    _Pragma("unroll") \
    for (int kk = 0; kk < 16; kk += 8) { \
        unsigned af[NMT][4]; unsigned bf[NNT][2]; \
        _Pragma("unroll") \
        for (int mt = 0; mt < NMT; mt++) { \
            int mr = wm + mt*16 + g; \
            af[mt][0] = As[mr][kk+t];   af[mt][1] = As[mr+8][kk+t]; \
            af[mt][2] = As[mr][kk+t+4]; af[mt][3] = As[mr+8][kk+t+4]; \
        } \
        _Pragma("unroll") \
        for (int nt = 0; nt < NNT; nt++) { \
            bf[nt][0] = Bs[kk+t][wn + nt*8 + g]; \
            bf[nt][1] = Bs[kk+t+4][wn + nt*8 + g]; \
        } \
        _Pragma("unroll") \
        for (int mt = 0; mt < NMT; mt++) \
            _Pragma("unroll") \
            for (int nt = 0; nt < NNT; nt++) \
                MMA(acc[mt][nt], af[mt], bf[nt]); \
    }

// ===========================================================================
// QKV projection (tf32 mma). Q/K: fp16 [B,H,S,64]. V: fp16 [B,H,64,S].
// ===========================================================================
__global__ void __launch_bounds__(256) qkv_kernel(
    const float* __restrict__ Qin, const float* __restrict__ Kin,
    const float* __restrict__ Vin,
    const float* __restrict__ Wq, const float* __restrict__ Wk,
    const float* __restrict__ Wv,
    const float* __restrict__ bq, const float* __restrict__ bk,
    const float* __restrict__ bv)
{
    __shared__ unsigned As[128][20];
    __shared__ unsigned Bs[16][136];

    const int z = blockIdx.z;
    const float* X    = (z == 0) ? Qin : (z == 1) ? Kin : Vin;
    const float* W    = (z == 0) ? Wq  : (z == 1) ? Wk  : Wv;
    const float* bias = (z == 0) ? bq  : (z == 1) ? bk  : bv;

    const int tid = threadIdx.x;
    const int lane = tid & 31, wid = tid >> 5;
    const int g = lane >> 2, t = lane & 3;
    const int wm = (wid & 1) << 6;
    const int wn = (wid >> 1) << 5;
    const int m0 = blockIdx.y * 128, n0 = blockIdx.x * 128;

    const int ar = tid >> 2, ak = (tid & 3) << 2;
    const int br = tid >> 5, bn = (tid & 31) << 2;

    const float* Ap = X + (size_t)(m0 + ar) * DM + ak;
    const float* Bp = W + (size_t)br * DM + n0 + bn;

    float acc[4][4][4] = {};
    float4 pa0, pa1, pb0, pb1;

    #define QKV_LDG(k0) do { \
        pa0 = *(const float4*)(Ap + (k0)); \
        pa1 = *(const float4*)(Ap + (size_t)64 * DM + (k0)); \
        pb0 = *(const float4*)(Bp + (size_t)(k0) * DM); \
        pb1 = *(const float4*)(Bp + (size_t)((k0) + 8) * DM); } while(0)

    #define QKV_STS() do { \
        *(uint4*)&As[ar][ak]    = make_uint4(tf32(pa0.x), tf32(pa0.y), tf32(pa0.z), tf32(pa0.w)); \
        *(uint4*)&As[ar+64][ak] = make_uint4(tf32(pa1.x), tf32(pa1.y), tf32(pa1.z), tf32(pa1.w)); \
        *(uint4*)&Bs[br][bn]    = make_uint4(tf32(pb0.x), tf32(pb0.y), tf32(pb0.z), tf32(pb0.w)); \
        *(uint4*)&Bs[br+8][bn]  = make_uint4(tf32(pb1.x), tf32(pb1.y), tf32(pb1.z), tf32(pb1.w)); } while(0)

    QKV_LDG(0);
    QKV_STS();
    __syncthreads();
    for (int k0 = 16; k0 < DM; k0 += 16) {
        QKV_LDG(k0);
        MMA_STEP(4, 4);
        __syncthreads();
        QKV_STS();
        __syncthreads();
    }
    MMA_STEP(4, 4);

    #pragma unroll
    for (int nt = 0; nt < 4; nt++) {
        int c = n0 + wn + nt*8 + 2*t;
        int h = c >> 6, d = c & 63;
        float2 bi = *(const float2*)(bias + c);
        #pragma unroll
        for (int mt = 0; mt < 4; mt++) {
            int r = m0 + wm + mt*16 + g;
            int b = r >> 11, s = r & (SEQ - 1);
            int bh = b * NH + h;
            float v0 = acc[mt][nt][0] + bi.x;
            float v1 = acc[mt][nt][1] + bi.y;
            float v2 = acc[mt][nt][2] + bi.x;
            float v3 = acc[mt][nt][3] + bi.y;
            if (z == 2) {
                half* vb = g_vh + ((size_t)bh * DHEAD + d) * SEQ;
                vb[s]          = __float2half(v0);
                vb[SEQ + s]    = __float2half(v1);
                vb[s + 8]      = __float2half(v2);
                vb[SEQ + s + 8]= __float2half(v3);
            } else {
                half* out = (z == 0) ? g_qh : g_kh;
                half* op = out + ((size_t)bh * SEQ + s) * DHEAD + d;
                *(unsigned*)op = h2pack(v0, v1);
                op += (size_t)8 * DHEAD;
                *(unsigned*)op = h2pack(v2, v3);
            }
        }
    }
}

// ===========================================================================
// Output projection (tf32 mma): g_x = g_ctx @ Wo + bo + residual.
// ===========================================================================
__global__ void __launch_bounds__(256) oproj_kernel(
    const float* __restrict__ W, const float* __restrict__ bias,
    const float* __restrict__ resid)
{
    __shared__ unsigned As[128][20];
    __shared__ unsigned Bs[16][136];

    const int tid = threadIdx.x;
    const int lane = tid & 31, wid = tid >> 5;
    const int g = lane >> 2, t = lane & 3;
    const int wm = (wid & 1) << 6;
    const int wn = (wid >> 1) << 5;
    const int m0 = blockIdx.y * 128, n0 = blockIdx.x * 128;

    const int ar = tid >> 2, ak = (tid & 3) << 2;
    const int br = tid >> 5, bn = (tid & 31) << 2;

    const float* Ap = g_ctx + (size_t)(m0 + ar) * DM + ak;
    const float* Bp = W + (size_t)br * DM + n0 + bn;

    float acc[4][4][4] = {};
    float4 pa0, pa1, pb0, pb1;

    QKV_LDG(0);
    QKV_STS();
    __syncthreads();
    for (int k0 = 16; k0 < DM; k0 += 16) {
        QKV_LDG(k0);
        MMA_STEP(4, 4);
        __syncthreads();
        QKV_STS();
        __syncthreads();
    }
    MMA_STEP(4, 4);

    #pragma unroll
    for (int nt = 0; nt < 4; nt++) {
        int c = n0 + wn + nt*8 + 2*t;
        float2 bi = *(const float2*)(bias + c);
        #pragma unroll
        for (int mt = 0; mt < 4; mt++) {
            int r = m0 + wm + mt*16 + g;
            float2 r0 = *(const float2*)(resid + (size_t)r * DM + c);
            float2 r1 = *(const float2*)(resid + (size_t)(r+8) * DM + c);
            *(float2*)(g_x + (size_t)r * DM + c) =
                make_float2(acc[mt][nt][0] + bi.x + r0.x, acc[mt][nt][1] + bi.y + r0.y);
            *(float2*)(g_x + (size_t)(r+8) * DM + c) =
                make_float2(acc[mt][nt][2] + bi.x + r1.x, acc[mt][nt][3] + bi.y + r1.y);
        }
    }
}

// ===========================================================================
// Fused attention v8: R13 structure (two-pass, 2 CTAs/SM) + ldmatrix
// fragment loads (x4 for A, x2 for B) replacing scalar LDS.
// 256 thr / 8 warps per CTA: 4 row-groups (16 q-rows) x 2 key-groups.
// Smem row pitches: Qs/Ks 144B, Vhs 272B — both conflict-free for LDSM.
// ===========================================================================
#define FA_QS   0
#define FA_KS   9216
#define FA_VH   46080
#define FA_RS   80896
#define FA_INV  81408
#define FA_SMEM 81664

__global__ void __launch_bounds__(256, 2) fused_attn_kernel(
    const unsigned char* __restrict__ mask, float* __restrict__ attn)
{
    extern __shared__ char smem[];
    float* rs   = (float*)(smem + FA_RS);    // [2][64]
    float* invp = (float*)(smem + FA_INV);   // [64]
    const unsigned sm_u = (unsigned)__cvta_generic_to_shared(smem);

    const int tid = threadIdx.x;
    const int lane = tid & 31, wid = tid >> 5;
    const int g = lane >> 2, t = lane & 3;
    const int wm = (wid & 3) << 4;     // q-row group: 0,16,32,48
    const int cg = wid >> 2;           // key-column group 0/1
    const int wn = cg << 6;            // key offset within tile: 0 or 64
    const int i0 = blockIdx.x * 64;
    const int bh = blockIdx.y;
    const int b = bh >> 4, h = bh & 15;

    const half* qbase = g_qh + ((size_t)bh * SEQ + i0) * DHEAD;
    const half* kbase = g_kh + (size_t)bh * SEQ * DHEAD;
    const half* vhbase = g_vh + (size_t)bh * DHEAD * SEQ;
    const unsigned char* mbase = mask + (size_t)b * SEQ * SEQ;
    float* abase = attn + (size_t)bh * SEQ * SEQ;

    // ldmatrix per-lane base addresses
    //  A (Qs, pitch 144B): row = wm + (lane&15), +16B col offset for lanes>=16
    const unsigned q_lm = sm_u + FA_QS + (unsigned)(wm + (lane & 15)) * 144u
                          + ((unsigned)(lane >> 4) << 4);
    //  B score (Ks, pitch 144B): row = wn + (lane&7), +16B for (lane>>3)&1
    const unsigned k_lm_row = (unsigned)(wn + (lane & 7)) * 144u
                          + (((unsigned)(lane >> 3) & 1u) << 4);
    //  B ctx (Vhs, pitch 272B): row = (lane&7), +16B for (lane>>3)&1
    const unsigned v_lm_row = (unsigned)(lane & 7) * 272u
                          + (((unsigned)(lane >> 3) & 1u) << 4);

    // Q tile (64 x 64 fp16 = 8KB): 512 chunks of 16B, 2 per thread
    #pragma unroll
    for (int c = 0; c < 2; c++) {
        int idx = tid + c * 256;
        int j = idx >> 3, ch = idx & 7;
        CPA16(sm_u + FA_QS + (j*36 + ch*4)*4, qbase + (size_t)j * DHEAD + ch*8);
    }
    CP_COMMIT();

    #define ISSUE_K(jt, bb) do { \
        _Pragma("unroll") \
        for (int c = 0; c < 4; c++) { \
            int idx = tid + c * 256; \
            int j = idx >> 3, ch = idx & 7; \
            CPA16(sm_u + FA_KS + (((bb)*128 + j)*36 + ch*4)*4, \
                  kbase + (size_t)((jt)*128 + j) * DHEAD + ch*8); \
        } } while(0)
    #define ISSUE_V(jt, bb) do { \
        _Pragma("unroll") \
        for (int c = 0; c < 4; c++) { \
            int idx = tid + c * 256; \
            int d = idx >> 4, ch = idx & 15; \
            CPA16(sm_u + FA_VH + (((bb)*64 + d)*68 + ch*4)*4, \
                  vhbase + (size_t)d * SEQ + (jt)*128 + ch*8); \
        } } while(0)

    // score mma: fp16 m16n8k16, warp tile 16m x 64n; ldmatrix fragments
    #define FA_SMMA(kb_base) do { \
        _Pragma("unroll") \
        for (int kh = 0; kh < 32; kh += 8) { \
            unsigned a0, a1, a2, a3; \
            LDSM_X4(a0, a1, a2, a3, q_lm + kh*4); \
            _Pragma("unroll") \
            for (int nt = 0; nt < 8; nt++) { \
                unsigned b0, b1; \
                LDSM_X2(b0, b1, (kb_base) + k_lm_row + nt*1152u + kh*4); \
                MMA16816(acc[nt], a0, a1, a2, a3, b0, b1); \
            } \
        } } while(0)

    ISSUE_K(0, 0);
    CP_COMMIT();

    const float scale = 0.125f;
    float p0 = 0.f, p1 = 0.f;

    // ---------------- PASS A: row sums ----------------
    for (int jt = 0; jt < 16; jt++) {
        if (jt < 15) ISSUE_K(jt+1, (jt+1)&1);
        CP_COMMIT();
        CP_WAIT1();
        __syncthreads();
        unsigned kb_base = sm_u + FA_KS + (unsigned)(jt & 1) * (128u * 144u);
        float acc[8][4] = {};
        FA_SMMA(kb_base);
        int j0 = jt * 128;
        #pragma unroll
        for (int nt = 0; nt < 8; nt++) {
            int cgc = j0 + wn + nt*8 + 2*t;
            int r0 = i0 + wm + g;
            uchar2 m0v = *(const uchar2*)(mbase + (size_t)r0 * SEQ + cgc);
            uchar2 m1v = *(const uchar2*)(mbase + (size_t)(r0+8) * SEQ + cgc);
            p0 += __expf(m0v.x ? -60.f : acc[nt][0]*scale)
                + __expf(m0v.y ? -60.f : acc[nt][1]*scale);
            p1 += __expf(m1v.x ? -60.f : acc[nt][2]*scale)
                + __expf(m1v.y ? -60.f : acc[nt][3]*scale);
        }
        __syncthreads();
    }

    // rowsum reduce: 4 lanes/row, then 2 key-groups via smem
    p0 += __shfl_xor_sync(0xffffffffu, p0, 1);
    p0 += __shfl_xor_sync(0xffffffffu, p0, 2);
    p1 += __shfl_xor_sync(0xffffffffu, p1, 1);
    p1 += __shfl_xor_sync(0xffffffffu, p1, 2);
    if (t == 0) {
        rs[cg*64 + wm + g]     = p0;
        rs[cg*64 + wm + g + 8] = p1;
    }
    __syncthreads();
    if (tid < 64) invp[tid] = 1.0f / (rs[tid] + rs[64 + tid]);

    ISSUE_K(0, 0);
    ISSUE_V(0, 0);
    CP_COMMIT();
    __syncthreads();   // invp visible

    const float iv0 = invp[wm + g];
    const float iv1 = invp[wm + g + 8];

    // ---------------- PASS B: emit attn + register-path P@V ----------------
    float cacc[8][4] = {};
    for (int jt = 0; jt < 16; jt++) {
        if (jt < 15) { ISSUE_K(jt+1, (jt+1)&1); ISSUE_V(jt+1, (jt+1)&1); }
        CP_COMMIT();
        CP_WAIT1();
        __syncthreads();
        unsigned kb_base = sm_u + FA_KS + (unsigned)(jt & 1) * (128u * 144u);
        unsigned vb_base = sm_u + FA_VH + (unsigned)(jt & 1) * (64u * 272u);
        float acc[8][4] = {};
        FA_SMMA(kb_base);
        int j0 = jt * 128;
        #pragma unroll
        for (int nt = 0; nt < 8; nt++) {
            int cgc = j0 + wn + nt*8 + 2*t;
            int r0 = i0 + wm + g;
            uchar2 m0v = *(const uchar2*)(mbase + (size_t)r0 * SEQ + cgc);
            uchar2 m1v = *(const uchar2*)(mbase + (size_t)(r0+8) * SEQ + cgc);
            float e0 = __expf(m0v.x ? -60.f : acc[nt][0]*scale) * iv0;
            float e1 = __expf(m0v.y ? -60.f : acc[nt][1]*scale) * iv0;
            float e2 = __expf(m1v.x ? -60.f : acc[nt][2]*scale) * iv1;
            float e3 = __expf(m1v.y ? -60.f : acc[nt][3]*scale) * iv1;
            *(float2*)(abase + (size_t)r0 * SEQ + cgc)     = make_float2(e0, e1);
            *(float2*)(abase + (size_t)(r0+8) * SEQ + cgc) = make_float2(e2, e3);
            acc[nt][0] = e0; acc[nt][1] = e1; acc[nt][2] = e2; acc[nt][3] = e3;
        }
        // ctx: cacc += P(16 x 64keys) @ V(64keys x 64d); ldmatrix B fragments
        #pragma unroll
        for (int kb = 0; kb < 4; kb++) {
            unsigned a0 = h2pack(acc[2*kb][0],   acc[2*kb][1]);
            unsigned a1 = h2pack(acc[2*kb][2],   acc[2*kb][3]);
            unsigned a2 = h2pack(acc[2*kb+1][0], acc[2*kb+1][1]);
            unsigned a3 = h2pack(acc[2*kb+1][2], acc[2*kb+1][3]);
            unsigned jb_off = (unsigned)((wn >> 1) + kb*8) * 4u;  // half2 word -> bytes
            #pragma unroll
            for (int nn = 0; nn < 8; nn++) {
                unsigned b0, b1;
                LDSM_X2(b0, b1, vb_base + (unsigned)nn * (8u*272u) + v_lm_row + jb_off);
                MMA16816(cacc[nn], a0, a1, a2, a3, b0, b1);
            }
        }
        __syncthreads();
    }

    // 2-way reduction of K-split context partials, then write g_ctx
    float (*red)[68] = (float(*)[68])(smem + FA_KS);
    if (cg == 1) {
        #pragma unroll
        for (int nn = 0; nn < 8; nn++) {
            red[wm+g][nn*8+2*t]     = cacc[nn][0];
            red[wm+g][nn*8+2*t+1]   = cacc[nn][1];
            red[wm+g+8][nn*8+2*t]   = cacc[nn][2];
            red[wm+g+8][nn*8+2*t+1] = cacc[nn][3];
        }
    }
    __syncthreads();
    if (cg == 0) {
        #pragma unroll
        for (int nn = 0; nn < 8; nn++) {
            int d = nn*8 + 2*t;
            int r = i0 + wm + g;
            size_t tok = (size_t)b * SEQ + r;
            *(float2*)(g_ctx + tok * DM + h*DHEAD + d) =
                make_float2(cacc[nn][0] + red[wm+g][d], cacc[nn][1] + red[wm+g][d+1]);
            *(float2*)(g_ctx + (tok+8) * DM + h*DHEAD + d) =
                make_float2(cacc[nn][2] + red[wm+g+8][d], cacc[nn][3] + red[wm+g+8][d+1]);
        }
    }
}

// ===========================================================================
// LayerNorm over g_x rows -> out region of d_out.
// ===========================================================================
__global__ void __launch_bounds__(256) ln_kernel(
    const float* __restrict__ gamma, const float* __restrict__ beta,
    float* __restrict__ out)
{
    const int tk = blockIdx.x;
    const int tid = threadIdx.x;
    float4 v = *(const float4*)(g_x + (size_t)tk * DM + (tid << 2));
    float s  = v.x + v.y + v.z + v.w;
    float ss = v.x*v.x + v.y*v.y + v.z*v.z + v.w*v.w;

    __shared__ float r1[8], r2[8];
    #pragma unroll
    for (int o = 16; o; o >>= 1) {
        s  += __shfl_xor_sync(0xffffffffu, s, o);
        ss += __shfl_xor_sync(0xffffffffu, ss, o);
    }
    if ((tid & 31) == 0) { r1[tid >> 5] = s; r2[tid >> 5] = ss; }
    __syncthreads();
    float ts = 0.f, tss = 0.f;
    #pragma unroll
    for (int w = 0; w < 8; w++) { ts += r1[w]; tss += r2[w]; }

    float mu  = ts * (1.0f / DM);
    float var = tss * (1.0f / DM) - mu * mu;
    float inv = rsqrtf(var + LN_EPS);

    float4 ga = *(const float4*)(gamma + (tid << 2));
    float4 be = *(const float4*)(beta  + (tid << 2));
    float4 o;
    o.x = (v.x - mu) * inv * ga.x + be.x;
    o.y = (v.y - mu) * inv * ga.y + be.y;
    o.z = (v.z - mu) * inv * ga.z + be.z;
    o.w = (v.w - mu) * inv * ga.w + be.w;
    *(float4*)(out + (size_t)tk * DM + (tid << 2)) = o;
}

// ===========================================================================
extern "C" void kernel_launch(void* const* d_in, const int* in_sizes, int n_in,
                              void* d_out, int out_size)
{
    const float* Q  = (const float*)d_in[0];
    const float* K  = (const float*)d_in[1];
    const float* V  = (const float*)d_in[2];
    const unsigned char* mask = (const unsigned char*)d_in[3];
    const float* Wq = (const float*)d_in[4];
    const float* bq = (const float*)d_in[5];
    const float* Wk = (const float*)d_in[6];
    const float* bk = (const float*)d_in[7];
    const float* Wv = (const float*)d_in[8];
    const float* bv = (const float*)d_in[9];
    const float* Wo = (const float*)d_in[10];
    const float* bo = (const float*)d_in[11];
    const float* gamma = (const float*)d_in[12];
    const float* beta  = (const float*)d_in[13];

    float* out  = (float*)d_out;
    float* attn = out + ATTN_OFF;

    cudaFuncSetAttribute(fused_attn_kernel,
                         cudaFuncAttributeMaxDynamicSharedMemorySize, FA_SMEM);

    qkv_kernel<<<dim3(DM/128, TTOK/128, 3), 256>>>(Q, K, V, Wq, Wk, Wv, bq, bk, bv);
    fused_attn_kernel<<<dim3(SEQ/64, BHN), 256, FA_SMEM>>>(mask, attn);
    oproj_kernel<<<dim3(DM/128, TTOK/128), 256>>>(Wo, bo, Q);
    ln_kernel<<<TTOK, 256>>>(gamma, beta, out);
}

// round 15
// speedup vs baseline: 1.3032x; 1.0329x over previous
#include <cuda_runtime.h>
#include <cuda_fp16.h>
#include <math.h>

#define BATCH 2
#define SEQ   2048
#define NH    16
#define DHEAD 64
#define DM    1024
#define TTOK  (BATCH*SEQ)
#define BHN   (BATCH*NH)
#define ATTN_OFF ((size_t)BATCH*SEQ*DM)
#define LN_EPS 1e-5f

__device__ half  g_qh[(size_t)BHN*SEQ*DHEAD];    // [B,H,S,64] fp16
__device__ half  g_kh[(size_t)BHN*SEQ*DHEAD];    // [B,H,S,64] fp16
__device__ half  g_vh[(size_t)BHN*DHEAD*SEQ];    // [B,H,64,S] fp16 transposed
__device__ half  g_p[(size_t)BHN*SEQ*SEQ];       // unnormalized exp scores (fp16)
__device__ float g_ctx[(size_t)TTOK*DM];          // [T, H*64]
__device__ float g_x[(size_t)TTOK*DM];            // pre-LN

__device__ __forceinline__ unsigned tf32(float f) {
    unsigned u;
    asm("cvt.rna.tf32.f32 %0, %1;" : "=r"(u) : "f"(f));
    return u;
}
__device__ __forceinline__ unsigned h2pack(float x, float y) {
    __half2 h = __floats2half2_rn(x, y);
    return *(unsigned*)&h;
}

#define MMA(d, a, b) \
    asm volatile("mma.sync.aligned.m16n8k8.row.col.f32.tf32.tf32.f32 " \
        "{%0,%1,%2,%3}, {%4,%5,%6,%7}, {%8,%9}, {%0,%1,%2,%3};" \
        : "+f"((d)[0]), "+f"((d)[1]), "+f"((d)[2]), "+f"((d)[3]) \
        : "r"((a)[0]), "r"((a)[1]), "r"((a)[2]), "r"((a)[3]), \
          "r"((b)[0]), "r"((b)[1]))

#define MMA16816(d, a0,a1,a2,a3, b0,b1) \
    asm volatile("mma.sync.aligned.m16n8k16.row.col.f32.f16.f16.f32 " \
        "{%0,%1,%2,%3}, {%4,%5,%6,%7}, {%8,%9}, {%0,%1,%2,%3};" \
        : "+f"((d)[0]), "+f"((d)[1]), "+f"((d)[2]), "+f"((d)[3]) \
        : "r"(a0), "r"(a1), "r"(a2), "r"(a3), "r"(b0), "r"(b1))

#define LDSM_X4(r0,r1,r2,r3, addr) \
    asm volatile("ldmatrix.sync.aligned.m8n8.x4.shared.b16 {%0,%1,%2,%3}, [%4];" \
        : "=r"(r0), "=r"(r1), "=r"(r2), "=r"(r3) : "r"(addr))
#define LDSM_X2(r0,r1, addr) \
    asm volatile("ldmatrix.sync.aligned.m8n8.x2.shared.b16 {%0,%1}, [%2];" \
        : "=r"(r0), "=r"(r1) : "r"(addr))

#define CPA16(dst, src) \
    asm volatile("cp.async.ca.shared.global [%0], [%1], 16;\n" \
        :: "r"((unsigned)(dst)), "l"((const void*)(src)))
#define CP_COMMIT() asm volatile("cp.async.commit_group;\n")
#define CP_WAIT1()  asm volatile("cp.async.wait_group 1;\n")

// One K=16 chunk of mma work for the projection kernels (As/Bs chunked).
#define MMA_STEP(NMT, NNT) \
    _Pragma("unroll") \
    for (int kk = 0; kk < 16; kk += 8) { \
        unsigned af[NMT][4]; unsigned bf[NNT][2]; \
        _Pragma("unroll") \
        for (int mt = 0; mt < NMT; mt++) { \
            int mr = wm + mt*16 + g; \
            af[mt][0] = As[mr][kk+t];   af[mt][1] = As[mr+8][kk+t]; \
            af[mt][2] = As[mr][kk+t+4]; af[mt][3] = As[mr+8][kk+t+4]; \
        } \
        _Pragma("unroll") \
        for (int nt = 0; nt < NNT; nt++) { \
            bf[nt][0] = Bs[kk+t][wn + nt*8 + g]; \
            bf[nt][1] = Bs[kk+t+4][wn + nt*8 + g]; \
        } \
        _Pragma("unroll") \
        for (int mt = 0; mt < NMT; mt++) \
            _Pragma("unroll") \
            for (int nt = 0; nt < NNT; nt++) \
                MMA(acc[mt][nt], af[mt], bf[nt]); \
    }

// ===========================================================================
// QKV projection (tf32 mma). Q/K: fp16 [B,H,S,64]. V: fp16 [B,H,64,S].
// ===========================================================================
__global__ void __launch_bounds__(256) qkv_kernel(
    const float* __restrict__ Qin, const float* __restrict__ Kin,
    const float* __restrict__ Vin,
    const float* __restrict__ Wq, const float* __restrict__ Wk,
    const float* __restrict__ Wv,
    const float* __restrict__ bq, const float* __restrict__ bk,
    const float* __restrict__ bv)
{
    __shared__ unsigned As[128][20];
    __shared__ unsigned Bs[16][136];

    const int z = blockIdx.z;
    const float* X    = (z == 0) ? Qin : (z == 1) ? Kin : Vin;
    const float* W    = (z == 0) ? Wq  : (z == 1) ? Wk  : Wv;
    const float* bias = (z == 0) ? bq  : (z == 1) ? bk  : bv;

    const int tid = threadIdx.x;
    const int lane = tid & 31, wid = tid >> 5;
    const int g = lane >> 2, t = lane & 3;
    const int wm = (wid & 1) << 6;
    const int wn = (wid >> 1) << 5;
    const int m0 = blockIdx.y * 128, n0 = blockIdx.x * 128;

    const int ar = tid >> 2, ak = (tid & 3) << 2;
    const int br = tid >> 5, bn = (tid & 31) << 2;

    const float* Ap = X + (size_t)(m0 + ar) * DM + ak;
    const float* Bp = W + (size_t)br * DM + n0 + bn;

    float acc[4][4][4] = {};
    float4 pa0, pa1, pb0, pb1;

    #define QKV_LDG(k0) do { \
        pa0 = *(const float4*)(Ap + (k0)); \
        pa1 = *(const float4*)(Ap + (size_t)64 * DM + (k0)); \
        pb0 = *(const float4*)(Bp + (size_t)(k0) * DM); \
        pb1 = *(const float4*)(Bp + (size_t)((k0) + 8) * DM); } while(0)

    #define QKV_STS() do { \
        *(uint4*)&As[ar][ak]    = make_uint4(tf32(pa0.x), tf32(pa0.y), tf32(pa0.z), tf32(pa0.w)); \
        *(uint4*)&As[ar+64][ak] = make_uint4(tf32(pa1.x), tf32(pa1.y), tf32(pa1.z), tf32(pa1.w)); \
        *(uint4*)&Bs[br][bn]    = make_uint4(tf32(pb0.x), tf32(pb0.y), tf32(pb0.z), tf32(pb0.w)); \
        *(uint4*)&Bs[br+8][bn]  = make_uint4(tf32(pb1.x), tf32(pb1.y), tf32(pb1.z), tf32(pb1.w)); } while(0)

    QKV_LDG(0);
    QKV_STS();
    __syncthreads();
    for (int k0 = 16; k0 < DM; k0 += 16) {
        QKV_LDG(k0);
        MMA_STEP(4, 4);
        __syncthreads();
        QKV_STS();
        __syncthreads();
    }
    MMA_STEP(4, 4);

    #pragma unroll
    for (int nt = 0; nt < 4; nt++) {
        int c = n0 + wn + nt*8 + 2*t;
        int h = c >> 6, d = c & 63;
        float2 bi = *(const float2*)(bias + c);
        #pragma unroll
        for (int mt = 0; mt < 4; mt++) {
            int r = m0 + wm + mt*16 + g;
            int b = r >> 11, s = r & (SEQ - 1);
            int bh = b * NH + h;
            float v0 = acc[mt][nt][0] + bi.x;
            float v1 = acc[mt][nt][1] + bi.y;
            float v2 = acc[mt][nt][2] + bi.x;
            float v3 = acc[mt][nt][3] + bi.y;
            if (z == 2) {
                half* vb = g_vh + ((size_t)bh * DHEAD + d) * SEQ;
                vb[s]          = __float2half(v0);
                vb[SEQ + s]    = __float2half(v1);
                vb[s + 8]      = __float2half(v2);
                vb[SEQ + s + 8]= __float2half(v3);
            } else {
                half* out = (z == 0) ? g_qh : g_kh;
                half* op = out + ((size_t)bh * SEQ + s) * DHEAD + d;
                *(unsigned*)op = h2pack(v0, v1);
                op += (size_t)8 * DHEAD;
                *(unsigned*)op = h2pack(v2, v3);
            }
        }
    }
}

// ===========================================================================
// Output projection (tf32 mma): g_x = g_ctx @ Wo + bo + residual.
// ===========================================================================
__global__ void __launch_bounds__(256) oproj_kernel(
    const float* __restrict__ W, const float* __restrict__ bias,
    const float* __restrict__ resid)
{
    __shared__ unsigned As[128][20];
    __shared__ unsigned Bs[16][136];

    const int tid = threadIdx.x;
    const int lane = tid & 31, wid = tid >> 5;
    const int g = lane >> 2, t = lane & 3;
    const int wm = (wid & 1) << 6;
    const int wn = (wid >> 1) << 5;
    const int m0 = blockIdx.y * 128, n0 = blockIdx.x * 128;

    const int ar = tid >> 2, ak = (tid & 3) << 2;
    const int br = tid >> 5, bn = (tid & 31) << 2;

    const float* Ap = g_ctx + (size_t)(m0 + ar) * DM + ak;
    const float* Bp = W + (size_t)br * DM + n0 + bn;

    float acc[4][4][4] = {};
    float4 pa0, pa1, pb0, pb1;

    QKV_LDG(0);
    QKV_STS();
    __syncthreads();
    for (int k0 = 16; k0 < DM; k0 += 16) {
        QKV_LDG(k0);
        MMA_STEP(4, 4);
        __syncthreads();
        QKV_STS();
        __syncthreads();
    }
    MMA_STEP(4, 4);

    #pragma unroll
    for (int nt = 0; nt < 4; nt++) {
        int c = n0 + wn + nt*8 + 2*t;
        float2 bi = *(const float2*)(bias + c);
        #pragma unroll
        for (int mt = 0; mt < 4; mt++) {
            int r = m0 + wm + mt*16 + g;
            float2 r0 = *(const float2*)(resid + (size_t)r * DM + c);
            float2 r1 = *(const float2*)(resid + (size_t)(r+8) * DM + c);
            *(float2*)(g_x + (size_t)r * DM + c) =
                make_float2(acc[mt][nt][0] + bi.x + r0.x, acc[mt][nt][1] + bi.y + r0.y);
            *(float2*)(g_x + (size_t)(r+8) * DM + c) =
                make_float2(acc[mt][nt][2] + bi.x + r1.x, acc[mt][nt][3] + bi.y + r1.y);
        }
    }
}

// ===========================================================================
// Fused attention v9: P-cache. Pass A computes exp scores once, stores
// unnormalized fp16 P to g_p (L2-resident round trip) + rowsums. Pass B
// streams P+V tiles: emits normalized attn (LDS+FMUL+STG only) and runs
// ctx mma with ldmatrix A-frags straight from the P smem tile. No score
// recompute, no exp chain, no mask in pass B. 2 CTAs/SM retained.
// ===========================================================================
#define FA_QS   0
#define FA_KS   9216
#define FA_VH   46080
#define FA_RS   80896
#define FA_INV  81408
#define FA_SMEM 81664

__global__ void __launch_bounds__(256, 2) fused_attn_kernel(
    const unsigned char* __restrict__ mask, float* __restrict__ attn)
{
    extern __shared__ char smem[];
    float* rs   = (float*)(smem + FA_RS);    // [2][64]
    float* invp = (float*)(smem + FA_INV);   // [64]
    const unsigned sm_u = (unsigned)__cvta_generic_to_shared(smem);

    const int tid = threadIdx.x;
    const int lane = tid & 31, wid = tid >> 5;
    const int g = lane >> 2, t = lane & 3;
    const int wm = (wid & 3) << 4;     // q-row group: 0,16,32,48
    const int cg = wid >> 2;           // key-column group 0/1
    const int wn = cg << 6;            // key offset within tile: 0 or 64
    const int i0 = blockIdx.x * 64;
    const int bh = blockIdx.y;
    const int b = bh >> 4, h = bh & 15;

    const half* qbase = g_qh + ((size_t)bh * SEQ + i0) * DHEAD;
    const half* kbase = g_kh + (size_t)bh * SEQ * DHEAD;
    const half* vhbase = g_vh + (size_t)bh * DHEAD * SEQ;
    half* pbase = g_p + ((size_t)bh * SEQ + i0) * SEQ;   // this CTA's 64 rows
    const unsigned char* mbase = mask + (size_t)b * SEQ * SEQ;
    float* abase = attn + (size_t)bh * SEQ * SEQ;

    // ldmatrix per-lane addresses
    const unsigned q_lm = sm_u + FA_QS + (unsigned)(wm + (lane & 15)) * 144u
                          + ((unsigned)(lane >> 4) << 4);
    const unsigned k_lm_row = (unsigned)(wn + (lane & 7)) * 144u
                          + (((unsigned)(lane >> 3) & 1u) << 4);
    const unsigned v_lm_row = (unsigned)(lane & 7) * 272u
                          + (((unsigned)(lane >> 3) & 1u) << 4);
    // P as A-operand (pitch 272B): row = wm + (lane&15), hi/lo 16B split
    const unsigned p_lm_row = (unsigned)(wm + (lane & 15)) * 272u
                          + ((unsigned)(lane >> 4) << 4);

    // Q tile (64 x 64 fp16 = 8KB)
    #pragma unroll
    for (int c = 0; c < 2; c++) {
        int idx = tid + c * 256;
        int j = idx >> 3, ch = idx & 7;
        CPA16(sm_u + FA_QS + (j*36 + ch*4)*4, qbase + (size_t)j * DHEAD + ch*8);
    }
    CP_COMMIT();

    #define ISSUE_K(jt, bb) do { \
        _Pragma("unroll") \
        for (int c = 0; c < 4; c++) { \
            int idx = tid + c * 256; \
            int j = idx >> 3, ch = idx & 7; \
            CPA16(sm_u + FA_KS + (((bb)*128 + j)*36 + ch*4)*4, \
                  kbase + (size_t)((jt)*128 + j) * DHEAD + ch*8); \
        } } while(0)
    #define ISSUE_V(jt, bb) do { \
        _Pragma("unroll") \
        for (int c = 0; c < 4; c++) { \
            int idx = tid + c * 256; \
            int d = idx >> 4, ch = idx & 15; \
            CPA16(sm_u + FA_VH + (((bb)*64 + d)*68 + ch*4)*4, \
                  vhbase + (size_t)d * SEQ + (jt)*128 + ch*8); \
        } } while(0)
    // P tile: 64 rows x 128 keys fp16, pitch 272B (reuses the K region)
    #define ISSUE_P(jt, bb) do { \
        _Pragma("unroll") \
        for (int c = 0; c < 4; c++) { \
            int idx = tid + c * 256; \
            int r = idx >> 4, ch = idx & 15; \
            CPA16(sm_u + FA_KS + ((bb)*64 + r)*272u + ch*16u, \
                  pbase + (size_t)r * SEQ + (jt)*128 + ch*8); \
        } } while(0)

    // score mma: fp16 m16n8k16, warp tile 16m x 64n; ldmatrix fragments
    #define FA_SMMA(kb_base) do { \
        _Pragma("unroll") \
        for (int kh = 0; kh < 32; kh += 8) { \
            unsigned a0, a1, a2, a3; \
            LDSM_X4(a0, a1, a2, a3, q_lm + kh*4); \
            _Pragma("unroll") \
            for (int nt = 0; nt < 8; nt++) { \
                unsigned b0, b1; \
                LDSM_X2(b0, b1, (kb_base) + k_lm_row + nt*1152u + kh*4); \
                MMA16816(acc[nt], a0, a1, a2, a3, b0, b1); \
            } \
        } } while(0)

    ISSUE_K(0, 0);
    CP_COMMIT();

    const float scale = 0.125f;
    float p0 = 0.f, p1 = 0.f;

    // ---------------- PASS A: rowsums + store fp16 P ----------------
    for (int jt = 0; jt < 16; jt++) {
        if (jt < 15) ISSUE_K(jt+1, (jt+1)&1);
        CP_COMMIT();
        CP_WAIT1();
        __syncthreads();
        unsigned kb_base = sm_u + FA_KS + (unsigned)(jt & 1) * (128u * 144u);
        float acc[8][4] = {};
        FA_SMMA(kb_base);
        int j0 = jt * 128;
        #pragma unroll
        for (int nt = 0; nt < 8; nt++) {
            int cgc = j0 + wn + nt*8 + 2*t;
            int r0 = i0 + wm + g;
            int rl = wm + g;
            uchar2 m0v = *(const uchar2*)(mbase + (size_t)r0 * SEQ + cgc);
            uchar2 m1v = *(const uchar2*)(mbase + (size_t)(r0+8) * SEQ + cgc);
            float e0 = __expf(m0v.x ? -60.f : acc[nt][0]*scale);
            float e1 = __expf(m0v.y ? -60.f : acc[nt][1]*scale);
            float e2 = __expf(m1v.x ? -60.f : acc[nt][2]*scale);
            float e3 = __expf(m1v.y ? -60.f : acc[nt][3]*scale);
            p0 += e0 + e1;
            p1 += e2 + e3;
            *(unsigned*)(pbase + (size_t)rl * SEQ + cgc)     = h2pack(e0, e1);
            *(unsigned*)(pbase + (size_t)(rl+8) * SEQ + cgc) = h2pack(e2, e3);
        }
        __syncthreads();
    }

    // rowsum reduce: 4 lanes/row, then 2 key-groups via smem
    p0 += __shfl_xor_sync(0xffffffffu, p0, 1);
    p0 += __shfl_xor_sync(0xffffffffu, p0, 2);
    p1 += __shfl_xor_sync(0xffffffffu, p1, 1);
    p1 += __shfl_xor_sync(0xffffffffu, p1, 2);
    if (t == 0) {
        rs[cg*64 + wm + g]     = p0;
        rs[cg*64 + wm + g + 8] = p1;
    }
    __syncthreads();
    if (tid < 64) invp[tid] = 1.0f / (rs[tid] + rs[64 + tid]);

    ISSUE_P(0, 0);
    ISSUE_V(0, 0);
    CP_COMMIT();
    __syncthreads();   // invp visible

    const float iv0 = invp[wm + g];
    const float iv1 = invp[wm + g + 8];

    // ---------------- PASS B: emit attn from P + ctx mma ----------------
    float cacc[8][4] = {};
    for (int jt = 0; jt < 16; jt++) {
        if (jt < 15) { ISSUE_P(jt+1, (jt+1)&1); ISSUE_V(jt+1, (jt+1)&1); }
        CP_COMMIT();
        CP_WAIT1();
        __syncthreads();
        const char* pb = smem + FA_KS + (size_t)(jt & 1) * (64u * 272u);
        unsigned pb_u = sm_u + FA_KS + (unsigned)(jt & 1) * (64u * 272u);
        unsigned vb_base = sm_u + FA_VH + (unsigned)(jt & 1) * (64u * 272u);
        int j0 = jt * 128;
        // emit normalized attn straight from smem P
        #pragma unroll
        for (int nt = 0; nt < 8; nt++) {
            int cl = wn + nt*8 + 2*t;
            int cgc = j0 + cl;
            int r0 = i0 + wm + g;
            float2 f0 = __half22float2(*(const __half2*)(pb + (wm+g)*272 + cl*2));
            float2 f1 = __half22float2(*(const __half2*)(pb + (wm+g+8)*272 + cl*2));
            *(float2*)(abase + (size_t)r0 * SEQ + cgc) =
                make_float2(f0.x * iv0, f0.y * iv0);
            *(float2*)(abase + (size_t)(r0+8) * SEQ + cgc) =
                make_float2(f1.x * iv1, f1.y * iv1);
        }
        // ctx: cacc += P(16 x 64keys) @ V(64keys x 64d); all frags via ldmatrix
        #pragma unroll
        for (int kb = 0; kb < 4; kb++) {
            unsigned a0, a1, a2, a3;
            LDSM_X4(a0, a1, a2, a3, pb_u + p_lm_row + (unsigned)wn*2u + kb*32u);
            unsigned jb_off = (unsigned)((wn >> 1) + kb*8) * 4u;
            #pragma unroll
            for (int nn = 0; nn < 8; nn++) {
                unsigned b0, b1;
                LDSM_X2(b0, b1, vb_base + (unsigned)nn * (8u*272u) + v_lm_row + jb_off);
                MMA16816(cacc[nn], a0, a1, a2, a3, b0, b1);
            }
        }
        __syncthreads();
    }

    // 2-way reduction of K-split context partials, normalize, write g_ctx
    float (*red)[68] = (float(*)[68])(smem + FA_KS);
    if (cg == 1) {
        #pragma unroll
        for (int nn = 0; nn < 8; nn++) {
            red[wm+g][nn*8+2*t]     = cacc[nn][0];
            red[wm+g][nn*8+2*t+1]   = cacc[nn][1];
            red[wm+g+8][nn*8+2*t]   = cacc[nn][2];
            red[wm+g+8][nn*8+2*t+1] = cacc[nn][3];
        }
    }
    __syncthreads();
    if (cg == 0) {
        #pragma unroll
        for (int nn = 0; nn < 8; nn++) {
            int d = nn*8 + 2*t;
            int r = i0 + wm + g;
            size_t tok = (size_t)b * SEQ + r;
            *(float2*)(g_ctx + tok * DM + h*DHEAD + d) =
                make_float2((cacc[nn][0] + red[wm+g][d])   * iv0,
                            (cacc[nn][1] + red[wm+g][d+1]) * iv0);
            *(float2*)(g_ctx + (tok+8) * DM + h*DHEAD + d) =
                make_float2((cacc[nn][2] + red[wm+g+8][d])   * iv1,
                            (cacc[nn][3] + red[wm+g+8][d+1]) * iv1);
        }
    }
}

// ===========================================================================
// LayerNorm over g_x rows -> out region of d_out.
// ===========================================================================
__global__ void __launch_bounds__(256) ln_kernel(
    const float* __restrict__ gamma, const float* __restrict__ beta,
    float* __restrict__ out)
{
    const int tk = blockIdx.x;
    const int tid = threadIdx.x;
    float4 v = *(const float4*)(g_x + (size_t)tk * DM + (tid << 2));
    float s  = v.x + v.y + v.z + v.w;
    float ss = v.x*v.x + v.y*v.y + v.z*v.z + v.w*v.w;

    __shared__ float r1[8], r2[8];
    #pragma unroll
    for (int o = 16; o; o >>= 1) {
        s  += __shfl_xor_sync(0xffffffffu, s, o);
        ss += __shfl_xor_sync(0xffffffffu, ss, o);
    }
    if ((tid & 31) == 0) { r1[tid >> 5] = s; r2[tid >> 5] = ss; }
    __syncthreads();
    float ts = 0.f, tss = 0.f;
    #pragma unroll
    for (int w = 0; w < 8; w++) { ts += r1[w]; tss += r2[w]; }

    float mu  = ts * (1.0f / DM);
    float var = tss * (1.0f / DM) - mu * mu;
    float inv = rsqrtf(var + LN_EPS);

    float4 ga = *(const float4*)(gamma + (tid << 2));
    float4 be = *(const float4*)(beta  + (tid << 2));
    float4 o;
    o.x = (v.x - mu) * inv * ga.x + be.x;
    o.y = (v.y - mu) * inv * ga.y + be.y;
    o.z = (v.z - mu) * inv * ga.z + be.z;
    o.w = (v.w - mu) * inv * ga.w + be.w;
    *(float4*)(out + (size_t)tk * DM + (tid << 2)) = o;
}

// ===========================================================================
extern "C" void kernel_launch(void* const* d_in, const int* in_sizes, int n_in,
                              void* d_out, int out_size)
{
    const float* Q  = (const float*)d_in[0];
    const float* K  = (const float*)d_in[1];
    const float* V  = (const float*)d_in[2];
    const unsigned char* mask = (const unsigned char*)d_in[3];
    const float* Wq = (const float*)d_in[4];
    const float* bq = (const float*)d_in[5];
    const float* Wk = (const float*)d_in[6];
    const float* bk = (const float*)d_in[7];
    const float* Wv = (const float*)d_in[8];
    const float* bv = (const float*)d_in[9];
    const float* Wo = (const float*)d_in[10];
    const float* bo = (const float*)d_in[11];
    const float* gamma = (const float*)d_in[12];
    const float* beta  = (const float*)d_in[13];

    float* out  = (float*)d_out;
    float* attn = out + ATTN_OFF;

    cudaFuncSetAttribute(fused_attn_kernel,
                         cudaFuncAttributeMaxDynamicSharedMemorySize, FA_SMEM);

    qkv_kernel<<<dim3(DM/128, TTOK/128, 3), 256>>>(Q, K, V, Wq, Wk, Wv, bq, bk, bv);
    fused_attn_kernel<<<dim3(SEQ/64, BHN), 256, FA_SMEM>>>(mask, attn);
    oproj_kernel<<<dim3(DM/128, TTOK/128), 256>>>(Wo, bo, Q);
    ln_kernel<<<TTOK, 256>>>(gamma, beta, out);
}

// round 17
// speedup vs baseline: 1.3749x; 1.0550x over previous
#include <cuda_runtime.h>
#include <cuda_fp16.h>
#include <math.h>

#define BATCH 2
#define SEQ   2048
#define NH    16
#define DHEAD 64
#define DM    1024
#define TTOK  (BATCH*SEQ)
#define BHN   (BATCH*NH)
#define ATTN_OFF ((size_t)BATCH*SEQ*DM)
#define LN_EPS 1e-5f

__device__ half  g_qh[(size_t)BHN*SEQ*DHEAD];    // [B,H,S,64] fp16
__device__ half  g_kh[(size_t)BHN*SEQ*DHEAD];    // [B,H,S,64] fp16
__device__ half  g_vh[(size_t)BHN*DHEAD*SEQ];    // [B,H,64,S] fp16 transposed
__device__ half  g_p[(size_t)BHN*SEQ*SEQ];       // unnormalized exp scores (fp16)
__device__ float g_ctx[(size_t)TTOK*DM];          // [T, H*64]
__device__ float g_x[(size_t)TTOK*DM];            // pre-LN

__device__ __forceinline__ unsigned tf32(float f) {
    unsigned u;
    asm("cvt.rna.tf32.f32 %0, %1;" : "=r"(u) : "f"(f));
    return u;
}
__device__ __forceinline__ unsigned h2pack(float x, float y) {
    __half2 h = __floats2half2_rn(x, y);
    return *(unsigned*)&h;
}

#define MMA(d, a, b) \
    asm volatile("mma.sync.aligned.m16n8k8.row.col.f32.tf32.tf32.f32 " \
        "{%0,%1,%2,%3}, {%4,%5,%6,%7}, {%8,%9}, {%0,%1,%2,%3};" \
        : "+f"((d)[0]), "+f"((d)[1]), "+f"((d)[2]), "+f"((d)[3]) \
        : "r"((a)[0]), "r"((a)[1]), "r"((a)[2]), "r"((a)[3]), \
          "r"((b)[0]), "r"((b)[1]))

#define MMA16816(d, a0,a1,a2,a3, b0,b1) \
    asm volatile("mma.sync.aligned.m16n8k16.row.col.f32.f16.f16.f32 " \
        "{%0,%1,%2,%3}, {%4,%5,%6,%7}, {%8,%9}, {%0,%1,%2,%3};" \
        : "+f"((d)[0]), "+f"((d)[1]), "+f"((d)[2]), "+f"((d)[3]) \
        : "r"(a0), "r"(a1), "r"(a2), "r"(a3), "r"(b0), "r"(b1))

#define LDSM_X4(r0,r1,r2,r3, addr) \
    asm volatile("ldmatrix.sync.aligned.m8n8.x4.shared.b16 {%0,%1,%2,%3}, [%4];" \
        : "=r"(r0), "=r"(r1), "=r"(r2), "=r"(r3) : "r"(addr))
#define LDSM_X2(r0,r1, addr) \
    asm volatile("ldmatrix.sync.aligned.m8n8.x2.shared.b16 {%0,%1}, [%2];" \
        : "=r"(r0), "=r"(r1) : "r"(addr))

#define CPA16(dst, src) \
    asm volatile("cp.async.ca.shared.global [%0], [%1], 16;\n" \
        :: "r"((unsigned)(dst)), "l"((const void*)(src)))
#define CP_COMMIT() asm volatile("cp.async.commit_group;\n")
#define CP_WAIT0()  asm volatile("cp.async.wait_group 0;\n")

// One K=16 chunk of mma work for the projection kernels (As/Bs chunked).
#define MMA_STEP(NMT, NNT) \
    _Pragma("unroll") \
    for (int kk = 0; kk < 16; kk += 8) { \
        unsigned af[NMT][4]; unsigned bf[NNT][2]; \
        _Pragma("unroll") \
        for (int mt = 0; mt < NMT; mt++) { \
            int mr = wm + mt*16 + g; \
            af[mt][0] = As[mr][kk+t];   af[mt][1] = As[mr+8][kk+t]; \
            af[mt][2] = As[mr][kk+t+4]; af[mt][3] = As[mr+8][kk+t+4]; \
        } \
        _Pragma("unroll") \
        for (int nt = 0; nt < NNT; nt++) { \
            bf[nt][0] = Bs[kk+t][wn + nt*8 + g]; \
            bf[nt][1] = Bs[kk+t+4][wn + nt*8 + g]; \
        } \
        _Pragma("unroll") \
        for (int mt = 0; mt < NMT; mt++) \
            _Pragma("unroll") \
            for (int nt = 0; nt < NNT; nt++) \
                MMA(acc[mt][nt], af[mt], bf[nt]); \
    }

// ===========================================================================
// QKV projection (tf32 mma). Q/K: fp16 [B,H,S,64]. V: fp16 [B,H,64,S].
// ===========================================================================
__global__ void __launch_bounds__(256) qkv_kernel(
    const float* __restrict__ Qin, const float* __restrict__ Kin,
    const float* __restrict__ Vin,
    const float* __restrict__ Wq, const float* __restrict__ Wk,
    const float* __restrict__ Wv,
    const float* __restrict__ bq, const float* __restrict__ bk,
    const float* __restrict__ bv)
{
    __shared__ unsigned As[128][20];
    __shared__ unsigned Bs[16][136];

    const int z = blockIdx.z;
    const float* X    = (z == 0) ? Qin : (z == 1) ? Kin : Vin;
    const float* W    = (z == 0) ? Wq  : (z == 1) ? Wk  : Wv;
    const float* bias = (z == 0) ? bq  : (z == 1) ? bk  : bv;

    const int tid = threadIdx.x;
    const int lane = tid & 31, wid = tid >> 5;
    const int g = lane >> 2, t = lane & 3;
    const int wm = (wid & 1) << 6;
    const int wn = (wid >> 1) << 5;
    const int m0 = blockIdx.y * 128, n0 = blockIdx.x * 128;

    const int ar = tid >> 2, ak = (tid & 3) << 2;
    const int br = tid >> 5, bn = (tid & 31) << 2;

    const float* Ap = X + (size_t)(m0 + ar) * DM + ak;
    const float* Bp = W + (size_t)br * DM + n0 + bn;

    float acc[4][4][4] = {};
    float4 pa0, pa1, pb0, pb1;

    #define QKV_LDG(k0) do { \
        pa0 = *(const float4*)(Ap + (k0)); \
        pa1 = *(const float4*)(Ap + (size_t)64 * DM + (k0)); \
        pb0 = *(const float4*)(Bp + (size_t)(k0) * DM); \
        pb1 = *(const float4*)(Bp + (size_t)((k0) + 8) * DM); } while(0)

    #define QKV_STS() do { \
        *(uint4*)&As[ar][ak]    = make_uint4(tf32(pa0.x), tf32(pa0.y), tf32(pa0.z), tf32(pa0.w)); \
        *(uint4*)&As[ar+64][ak] = make_uint4(tf32(pa1.x), tf32(pa1.y), tf32(pa1.z), tf32(pa1.w)); \
        *(uint4*)&Bs[br][bn]    = make_uint4(tf32(pb0.x), tf32(pb0.y), tf32(pb0.z), tf32(pb0.w)); \
        *(uint4*)&Bs[br+8][bn]  = make_uint4(tf32(pb1.x), tf32(pb1.y), tf32(pb1.z), tf32(pb1.w)); } while(0)

    QKV_LDG(0);
    QKV_STS();
    __syncthreads();
    for (int k0 = 16; k0 < DM; k0 += 16) {
        QKV_LDG(k0);
        MMA_STEP(4, 4);
        __syncthreads();
        QKV_STS();
        __syncthreads();
    }
    MMA_STEP(4, 4);

    #pragma unroll
    for (int nt = 0; nt < 4; nt++) {
        int c = n0 + wn + nt*8 + 2*t;
        int h = c >> 6, d = c & 63;
        float2 bi = *(const float2*)(bias + c);
        #pragma unroll
        for (int mt = 0; mt < 4; mt++) {
            int r = m0 + wm + mt*16 + g;
            int b = r >> 11, s = r & (SEQ - 1);
            int bh = b * NH + h;
            float v0 = acc[mt][nt][0] + bi.x;
            float v1 = acc[mt][nt][1] + bi.y;
            float v2 = acc[mt][nt][2] + bi.x;
            float v3 = acc[mt][nt][3] + bi.y;
            if (z == 2) {
                half* vb = g_vh + ((size_t)bh * DHEAD + d) * SEQ;
                vb[s]          = __float2half(v0);
                vb[SEQ + s]    = __float2half(v1);
                vb[s + 8]      = __float2half(v2);
                vb[SEQ + s + 8]= __float2half(v3);
            } else {
                half* out = (z == 0) ? g_qh : g_kh;
                half* op = out + ((size_t)bh * SEQ + s) * DHEAD + d;
                *(unsigned*)op = h2pack(v0, v1);
                op += (size_t)8 * DHEAD;
                *(unsigned*)op = h2pack(v2, v3);
            }
        }
    }
}

// ===========================================================================
// Output projection (tf32 mma): g_x = g_ctx @ Wo + bo + residual.
// ===========================================================================
__global__ void __launch_bounds__(256) oproj_kernel(
    const float* __restrict__ W, const float* __restrict__ bias,
    const float* __restrict__ resid)
{
    __shared__ unsigned As[128][20];
    __shared__ unsigned Bs[16][136];

    const int tid = threadIdx.x;
    const int lane = tid & 31, wid = tid >> 5;
    const int g = lane >> 2, t = lane & 3;
    const int wm = (wid & 1) << 6;
    const int wn = (wid >> 1) << 5;
    const int m0 = blockIdx.y * 128, n0 = blockIdx.x * 128;

    const int ar = tid >> 2, ak = (tid & 3) << 2;
    const int br = tid >> 5, bn = (tid & 31) << 2;

    const float* Ap = g_ctx + (size_t)(m0 + ar) * DM + ak;
    const float* Bp = W + (size_t)br * DM + n0 + bn;

    float acc[4][4][4] = {};
    float4 pa0, pa1, pb0, pb1;

    QKV_LDG(0);
    QKV_STS();
    __syncthreads();
    for (int k0 = 16; k0 < DM; k0 += 16) {
        QKV_LDG(k0);
        MMA_STEP(4, 4);
        __syncthreads();
        QKV_STS();
        __syncthreads();
    }
    MMA_STEP(4, 4);

    #pragma unroll
    for (int nt = 0; nt < 4; nt++) {
        int c = n0 + wn + nt*8 + 2*t;
        float2 bi = *(const float2*)(bias + c);
        #pragma unroll
        for (int mt = 0; mt < 4; mt++) {
            int r = m0 + wm + mt*16 + g;
            float2 r0 = *(const float2*)(resid + (size_t)r * DM + c);
            float2 r1 = *(const float2*)(resid + (size_t)(r+8) * DM + c);
            *(float2*)(g_x + (size_t)r * DM + c) =
                make_float2(acc[mt][nt][0] + bi.x + r0.x, acc[mt][nt][1] + bi.y + r0.y);
            *(float2*)(g_x + (size_t)(r+8) * DM + c) =
                make_float2(acc[mt][nt][2] + bi.x + r1.x, acc[mt][nt][3] + bi.y + r1.y);
        }
    }
}

// ===========================================================================
// Fused attention v10: P-cache + single-sync-per-tile pipeline
// (CP_WAIT0 -> sync -> issue next -> consume) + vectorized coalesced
// attn emit (warp-per-row, STG.128). 2 CTAs/SM.
// ===========================================================================
#define FA_QS   0
#define FA_KS   9216
#define FA_VH   46080
#define FA_RS   80896
#define FA_INV  81408
#define FA_SMEM 81664

__global__ void __launch_bounds__(256, 2) fused_attn_kernel(
    const unsigned char* __restrict__ mask, float* __restrict__ attn)
{
    extern __shared__ char smem[];
    float* rs   = (float*)(smem + FA_RS);    // [2][64]
    float* invp = (float*)(smem + FA_INV);   // [64]
    const unsigned sm_u = (unsigned)__cvta_generic_to_shared(smem);

    const int tid = threadIdx.x;
    const int lane = tid & 31, wid = tid >> 5;
    const int g = lane >> 2, t = lane & 3;
    const int wm = (wid & 3) << 4;     // q-row group: 0,16,32,48
    const int cg = wid >> 2;           // key-column group 0/1
    const int wn = cg << 6;            // key offset within tile: 0 or 64
    const int i0 = blockIdx.x * 64;
    const int bh = blockIdx.y;
    const int b = bh >> 4, h = bh & 15;

    const half* qbase = g_qh + ((size_t)bh * SEQ + i0) * DHEAD;
    const half* kbase = g_kh + (size_t)bh * SEQ * DHEAD;
    const half* vhbase = g_vh + (size_t)bh * DHEAD * SEQ;
    half* pbase = g_p + ((size_t)bh * SEQ + i0) * SEQ;   // this CTA's 64 rows
    const unsigned char* mbase = mask + (size_t)b * SEQ * SEQ;
    float* abase = attn + (size_t)bh * SEQ * SEQ;

    // ldmatrix per-lane addresses
    const unsigned q_lm = sm_u + FA_QS + (unsigned)(wm + (lane & 15)) * 144u
                          + ((unsigned)(lane >> 4) << 4);
    const unsigned k_lm_row = (unsigned)(wn + (lane & 7)) * 144u
                          + (((unsigned)(lane >> 3) & 1u) << 4);
    const unsigned v_lm_row = (unsigned)(lane & 7) * 272u
                          + (((unsigned)(lane >> 3) & 1u) << 4);
    const unsigned p_lm_row = (unsigned)(wm + (lane & 15)) * 272u
                          + ((unsigned)(lane >> 4) << 4);

    // Q tile (64 x 64 fp16 = 8KB)
    #pragma unroll
    for (int c = 0; c < 2; c++) {
        int idx = tid + c * 256;
        int j = idx >> 3, ch = idx & 7;
        CPA16(sm_u + FA_QS + (j*36 + ch*4)*4, qbase + (size_t)j * DHEAD + ch*8);
    }

    #define ISSUE_K(jt, bb) do { \
        _Pragma("unroll") \
        for (int c = 0; c < 4; c++) { \
            int idx = tid + c * 256; \
            int j = idx >> 3, ch = idx & 7; \
            CPA16(sm_u + FA_KS + (((bb)*128 + j)*36 + ch*4)*4, \
                  kbase + (size_t)((jt)*128 + j) * DHEAD + ch*8); \
        } } while(0)
    #define ISSUE_V(jt, bb) do { \
        _Pragma("unroll") \
        for (int c = 0; c < 4; c++) { \
            int idx = tid + c * 256; \
            int d = idx >> 4, ch = idx & 15; \
            CPA16(sm_u + FA_VH + (((bb)*64 + d)*68 + ch*4)*4, \
                  vhbase + (size_t)d * SEQ + (jt)*128 + ch*8); \
        } } while(0)
    // P tile: 64 rows x 128 keys fp16, pitch 272B (reuses the K region)
    #define ISSUE_P(jt, bb) do { \
        _Pragma("unroll") \
        for (int c = 0; c < 4; c++) { \
            int idx = tid + c * 256; \
            int r = idx >> 4, ch = idx & 15; \
            CPA16(sm_u + FA_KS + ((bb)*64 + r)*272u + ch*16u, \
                  pbase + (size_t)r * SEQ + (jt)*128 + ch*8); \
        } } while(0)

    // score mma: fp16 m16n8k16, warp tile 16m x 64n; ldmatrix fragments
    #define FA_SMMA(kb_base) do { \
        _Pragma("unroll") \
        for (int kh = 0; kh < 32; kh += 8) { \
            unsigned a0, a1, a2, a3; \
            LDSM_X4(a0, a1, a2, a3, q_lm + kh*4); \
            _Pragma("unroll") \
            for (int nt = 0; nt < 8; nt++) { \
                unsigned b0, b1; \
                LDSM_X2(b0, b1, (kb_base) + k_lm_row + nt*1152u + kh*4); \
                MMA16816(acc[nt], a0, a1, a2, a3, b0, b1); \
            } \
        } } while(0)

    ISSUE_K(0, 0);
    CP_COMMIT();

    const float scale = 0.125f;
    float p0 = 0.f, p1 = 0.f;

    // ---------------- PASS A: rowsums + store fp16 P ----------------
    // pipeline: WAIT0 -> sync -> issue next -> consume (single sync/tile)
    for (int jt = 0; jt < 16; jt++) {
        CP_WAIT0();
        __syncthreads();
        if (jt < 15) { ISSUE_K(jt+1, (jt+1)&1); CP_COMMIT(); }
        unsigned kb_base = sm_u + FA_KS + (unsigned)(jt & 1) * (128u * 144u);
        float acc[8][4] = {};
        FA_SMMA(kb_base);
        int j0 = jt * 128;
        #pragma unroll
        for (int nt = 0; nt < 8; nt++) {
            int cgc = j0 + wn + nt*8 + 2*t;
            int r0 = i0 + wm + g;
            int rl = wm + g;
            uchar2 m0v = *(const uchar2*)(mbase + (size_t)r0 * SEQ + cgc);
            uchar2 m1v = *(const uchar2*)(mbase + (size_t)(r0+8) * SEQ + cgc);
            float e0 = __expf(m0v.x ? -60.f : acc[nt][0]*scale);
            float e1 = __expf(m0v.y ? -60.f : acc[nt][1]*scale);
            float e2 = __expf(m1v.x ? -60.f : acc[nt][2]*scale);
            float e3 = __expf(m1v.y ? -60.f : acc[nt][3]*scale);
            p0 += e0 + e1;
            p1 += e2 + e3;
            *(unsigned*)(pbase + (size_t)rl * SEQ + cgc)     = h2pack(e0, e1);
            *(unsigned*)(pbase + (size_t)(rl+8) * SEQ + cgc) = h2pack(e2, e3);
        }
    }

    // rowsum reduce: 4 lanes/row, then 2 key-groups via smem
    p0 += __shfl_xor_sync(0xffffffffu, p0, 1);
    p0 += __shfl_xor_sync(0xffffffffu, p0, 2);
    p1 += __shfl_xor_sync(0xffffffffu, p1, 1);
    p1 += __shfl_xor_sync(0xffffffffu, p1, 2);
    __syncthreads();   // all pass-A smem reads done before reduction reuse
    if (t == 0) {
        rs[cg*64 + wm + g]     = p0;
        rs[cg*64 + wm + g + 8] = p1;
    }
    __syncthreads();
    if (tid < 64) invp[tid] = 1.0f / (rs[tid] + rs[64 + tid]);

    ISSUE_P(0, 0);
    ISSUE_V(0, 0);
    CP_COMMIT();
    __syncthreads();   // invp visible

    const float iv0 = invp[wm + g];
    const float iv1 = invp[wm + g + 8];

    // ---------------- PASS B: emit attn from P + ctx mma ----------------
    float cacc[8][4] = {};
    for (int jt = 0; jt < 16; jt++) {
        CP_WAIT0();
        __syncthreads();
        if (jt < 15) { ISSUE_P(jt+1, (jt+1)&1); ISSUE_V(jt+1, (jt+1)&1); CP_COMMIT(); }
        const char* pb = smem + FA_KS + (size_t)(jt & 1) * (64u * 272u);
        unsigned pb_u = sm_u + FA_KS + (unsigned)(jt & 1) * (64u * 272u);
        unsigned vb_base = sm_u + FA_VH + (unsigned)(jt & 1) * (64u * 272u);
        int j0 = jt * 128;
        // emit normalized attn: warp = one row, lane = 16B chunk (STG.128)
        #pragma unroll
        for (int it = 0; it < 8; it++) {
            int row = it*8 + wid;
            float iv = invp[row];
            const __half2* ph = (const __half2*)(pb + row*272 + lane*8);
            float2 f0 = __half22float2(ph[0]);
            float2 f1 = __half22float2(ph[1]);
            float4 o = make_float4(f0.x*iv, f0.y*iv, f1.x*iv, f1.y*iv);
            *(float4*)(abase + (size_t)(i0 + row) * SEQ + j0 + lane*4) = o;
        }
        // ctx: cacc += P(16 x 64keys) @ V(64keys x 64d); all frags via ldmatrix
        #pragma unroll
        for (int kb = 0; kb < 4; kb++) {
            unsigned a0, a1, a2, a3;
            LDSM_X4(a0, a1, a2, a3, pb_u + p_lm_row + (unsigned)wn*2u + kb*32u);
            unsigned jb_off = (unsigned)((wn >> 1) + kb*8) * 4u;
            #pragma unroll
            for (int nn = 0; nn < 8; nn++) {
                unsigned b0, b1;
                LDSM_X2(b0, b1, vb_base + (unsigned)nn * (8u*272u) + v_lm_row + jb_off);
                MMA16816(cacc[nn], a0, a1, a2, a3, b0, b1);
            }
        }
    }
    __syncthreads();   // pass-B smem reads done before reduction reuse

    // 2-way reduction of K-split context partials, normalize, write g_ctx
    float (*red)[68] = (float(*)[68])(smem + FA_KS);
    if (cg == 1) {
        #pragma unroll
        for (int nn = 0; nn < 8; nn++) {
            red[wm+g][nn*8+2*t]     = cacc[nn][0];
            red[wm+g][nn*8+2*t+1]   = cacc[nn][1];
            red[wm+g+8][nn*8+2*t]   = cacc[nn][2];
            red[wm+g+8][nn*8+2*t+1] = cacc[nn][3];
        }
    }
    __syncthreads();
    if (cg == 0) {
        #pragma unroll
        for (int nn = 0; nn < 8; nn++) {
            int d = nn*8 + 2*t;
            int r = i0 + wm + g;
            size_t tok = (size_t)b * SEQ + r;
            *(float2*)(g_ctx + tok * DM + h*DHEAD + d) =
                make_float2((cacc[nn][0] + red[wm+g][d])   * iv0,
                            (cacc[nn][1] + red[wm+g][d+1]) * iv0);
            *(float2*)(g_ctx + (tok+8) * DM + h*DHEAD + d) =
                make_float2((cacc[nn][2] + red[wm+g+8][d])   * iv1,
                            (cacc[nn][3] + red[wm+g+8][d+1]) * iv1);
        }
    }
}

// ===========================================================================
// LayerNorm over g_x rows -> out region of d_out.
// ===========================================================================
__global__ void __launch_bounds__(256) ln_kernel(
    const float* __restrict__ gamma, const float* __restrict__ beta,
    float* __restrict__ out)
{
    const int tk = blockIdx.x;
    const int tid = threadIdx.x;
    float4 v = *(const float4*)(g_x + (size_t)tk * DM + (tid << 2));
    float s  = v.x + v.y + v.z + v.w;
    float ss = v.x*v.x + v.y*v.y + v.z*v.z + v.w*v.w;

    __shared__ float r1[8], r2[8];
    #pragma unroll
    for (int o = 16; o; o >>= 1) {
        s  += __shfl_xor_sync(0xffffffffu, s, o);
        ss += __shfl_xor_sync(0xffffffffu, ss, o);
    }
    if ((tid & 31) == 0) { r1[tid >> 5] = s; r2[tid >> 5] = ss; }
    __syncthreads();
    float ts = 0.f, tss = 0.f;
    #pragma unroll
    for (int w = 0; w < 8; w++) { ts += r1[w]; tss += r2[w]; }

    float mu  = ts * (1.0f / DM);
    float var = tss * (1.0f / DM) - mu * mu;
    float inv = rsqrtf(var + LN_EPS);

    float4 ga = *(const float4*)(gamma + (tid << 2));
    float4 be = *(const float4*)(beta  + (tid << 2));
    float4 o;
    o.x = (v.x - mu) * inv * ga.x + be.x;
    o.y = (v.y - mu) * inv * ga.y + be.y;
    o.z = (v.z - mu) * inv * ga.z + be.z;
    o.w = (v.w - mu) * inv * ga.w + be.w;
    *(float4*)(out + (size_t)tk * DM + (tid << 2)) = o;
}

// ===========================================================================
extern "C" void kernel_launch(void* const* d_in, const int* in_sizes, int n_in,
                              void* d_out, int out_size)
{
    const float* Q  = (const float*)d_in[0];
    const float* K  = (const float*)d_in[1];
    const float* V  = (const float*)d_in[2];
    const unsigned char* mask = (const unsigned char*)d_in[3];
    const float* Wq = (const float*)d_in[4];
    const float* bq = (const float*)d_in[5];
    const float* Wk = (const float*)d_in[6];
    const float* bk = (const float*)d_in[7];
    const float* Wv = (const float*)d_in[8];
    const float* bv = (const float*)d_in[9];
    const float* Wo = (const float*)d_in[10];
    const float* bo = (const float*)d_in[11];
    const float* gamma = (const float*)d_in[12];
    const float* beta  = (const float*)d_in[13];

    float* out  = (float*)d_out;
    float* attn = out + ATTN_OFF;

    cudaFuncSetAttribute(fused_attn_kernel,
                         cudaFuncAttributeMaxDynamicSharedMemorySize, FA_SMEM);

    qkv_kernel<<<dim3(DM/128, TTOK/128, 3), 256>>>(Q, K, V, Wq, Wk, Wv, bq, bk, bv);
    fused_attn_kernel<<<dim3(SEQ/64, BHN), 256, FA_SMEM>>>(mask, attn);
    oproj_kernel<<<dim3(DM/128, TTOK/128), 256>>>(Wo, bo, Q);
    ln_kernel<<<TTOK, 256>>>(gamma, beta, out);
}